// round 4
// baseline (speedup 1.0000x reference)
#include <cuda_runtime.h>
#include <math.h>

#define NB 32
#define CDIM 1024
#define FE 16
#define NANC 9
#define KTOP 30
#define NROI (NB*KTOP)
#define PROJD 256
#define OC 512
#define NPOS (FE*FE)
#define MROWS (NB*NPOS)

__device__ float g_S[MROWS*CDIM];
__device__ float g_Wt[9*CDIM*OC];
__device__ float g_X[MROWS*OC];
__device__ float g_scores[NB*NPOS*NANC];
__device__ float g_boxes[NB*NPOS*NANC*4];
__device__ float g_rois[NROI*4];
__device__ int   g_valid[NROI];
__device__ float g_I[NB*257*257];
__device__ float g_pooled[NROI*CDIM];
__device__ float g_h[NROI*PROJD];
__device__ float g_proj[NROI*PROJD];
__device__ float g_nf[NROI*PROJD];
__device__ int   g_labels[NROI];
__device__ float g_rowl[NROI];
__device__ int   g_rowact[NROI];

// 1. spatial rearrange: clip[1+p][b][c] -> S[(b*256+p)*1024+c]
__global__ void build_spatial_kernel(const float* __restrict__ clip) {
  int bx = blockIdx.x; int b = bx >> 8, p = bx & 255;
  const float4* src = (const float4*)(clip + (size_t)(1+p)*NB*CDIM + (size_t)b*CDIM);
  ((float4*)(g_S + (size_t)bx*CDIM))[threadIdx.x] = src[threadIdx.x];
}

// 2. weights: conv_w[o][c][t] -> Wt[t][c][o]
__global__ void transpose_w_kernel(const float* __restrict__ conv_w) {
  int e = blockIdx.x*256 + threadIdx.x; // < 512*1024
  int o = e & 511, c = e >> 9;
  const float* src = conv_w + ((size_t)o*CDIM + c)*9;
#pragma unroll
  for (int t = 0; t < 9; t++) g_Wt[((size_t)t*CDIM + c)*OC + o] = src[t];
}

// 3. conv 3x3 as implicit GEMM, bias+relu. 128x128 tile, 256 thr, 8x8 acc.
__global__ __launch_bounds__(256) void conv_gemm_kernel(const float* __restrict__ convb) {
  const int bn = blockIdx.x*128, bm = blockIdx.y*128, tid = threadIdx.x;
  __shared__ float As[2][16][132];
  __shared__ float Bs[2][16][128];
  const int ar0 = tid>>2, ak4 = (tid&3)<<2;
  const int m0 = bm+ar0, m1 = m0+64;
  const int b0 = m0>>8, i0r = (m0>>4)&15, j0r = m0&15;
  const int b1 = m1>>8, i1r = (m1>>4)&15, j1r = m1&15;
  const int bk = tid>>5, bo = (tid&31)<<2;
  const int tm = (tid>>4)<<3, tn = (tid&15)<<3;
  float acc[8][8];
#pragma unroll
  for (int r=0;r<8;r++)
#pragma unroll
    for (int c=0;c<8;c++) acc[r][c]=0.f;
  float4 ra0, ra1, rb0, rb1;
  const int NS = 9*64;
  auto load_stage = [&](int s){
    int t = s>>6, k0 = (s&63)<<4;
    int di = t/3-1, dj = t-(t/3)*3-1;
    int ii = i0r+di, jj = j0r+dj;
    ra0 = ((unsigned)ii<16u && (unsigned)jj<16u) ?
      *(const float4*)&g_S[(size_t)((b0<<8)+(ii<<4)+jj)*CDIM + k0+ak4] : make_float4(0,0,0,0);
    ii = i1r+di; jj = j1r+dj;
    ra1 = ((unsigned)ii<16u && (unsigned)jj<16u) ?
      *(const float4*)&g_S[(size_t)((b1<<8)+(ii<<4)+jj)*CDIM + k0+ak4] : make_float4(0,0,0,0);
    rb0 = *(const float4*)&g_Wt[((size_t)t*CDIM + k0+bk)*OC + bn+bo];
    rb1 = *(const float4*)&g_Wt[((size_t)t*CDIM + k0+bk+8)*OC + bn+bo];
  };
  auto store_stage = [&](int buf){
    As[buf][ak4+0][ar0]=ra0.x; As[buf][ak4+1][ar0]=ra0.y;
    As[buf][ak4+2][ar0]=ra0.z; As[buf][ak4+3][ar0]=ra0.w;
    As[buf][ak4+0][ar0+64]=ra1.x; As[buf][ak4+1][ar0+64]=ra1.y;
    As[buf][ak4+2][ar0+64]=ra1.z; As[buf][ak4+3][ar0+64]=ra1.w;
    *(float4*)&Bs[buf][bk][bo]=rb0; *(float4*)&Bs[buf][bk+8][bo]=rb1;
  };
  load_stage(0); store_stage(0); __syncthreads();
  for (int s=0;s<NS;s++) {
    int buf = s&1;
    if (s+1<NS) load_stage(s+1);
#pragma unroll
    for (int kk=0;kk<16;kk++) {
      float4 a0=*(const float4*)&As[buf][kk][tm];
      float4 a1=*(const float4*)&As[buf][kk][tm+4];
      float4 q0=*(const float4*)&Bs[buf][kk][tn];
      float4 q1=*(const float4*)&Bs[buf][kk][tn+4];
      float av[8]={a0.x,a0.y,a0.z,a0.w,a1.x,a1.y,a1.z,a1.w};
      float bv[8]={q0.x,q0.y,q0.z,q0.w,q1.x,q1.y,q1.z,q1.w};
#pragma unroll
      for (int r=0;r<8;r++)
#pragma unroll
        for (int c=0;c<8;c++) acc[r][c] += av[r]*bv[c];
    }
    if (s+1<NS) store_stage((s+1)&1);
    __syncthreads();
  }
#pragma unroll
  for (int r=0;r<8;r++) {
    size_t off = (size_t)(bm+tm+r)*OC + bn+tn;
#pragma unroll
    for (int c=0;c<8;c++) g_X[off+c] = fmaxf(acc[r][c] + convb[bn+tn+c], 0.f);
  }
}

// 4. heads + anchor decode + sigmoid. One warp per position.
__global__ void heads_kernel(const float* __restrict__ cls_w, const float* __restrict__ cls_b,
                             const float* __restrict__ reg_w, const float* __restrict__ reg_b) {
  int w = threadIdx.x>>5, lane = threadIdx.x&31;
  int m = blockIdx.x*8 + w;
  float ac[9], ar[36];
#pragma unroll
  for (int a=0;a<9;a++) ac[a]=0.f;
#pragma unroll
  for (int a=0;a<36;a++) ar[a]=0.f;
  const float* xr = g_X + (size_t)m*OC;
  for (int c=lane;c<OC;c+=32) {
    float xv = xr[c];
#pragma unroll
    for (int a=0;a<9;a++) ac[a] += xv*cls_w[a*OC+c];
#pragma unroll
    for (int a=0;a<36;a++) ar[a] += xv*reg_w[a*OC+c];
  }
  __shared__ float hs[8][46];
#pragma unroll
  for (int a=0;a<9;a++){ float v=ac[a];
    for (int o=16;o>0;o>>=1) v += __shfl_xor_sync(0xffffffffu,v,o);
    if (lane==0) hs[w][a]=v; }
#pragma unroll
  for (int a=0;a<36;a++){ float v=ar[a];
    for (int o=16;o>0;o>>=1) v += __shfl_xor_sync(0xffffffffu,v,o);
    if (lane==0) hs[w][9+a]=v; }
  __syncwarp();
  if (lane<9) {
    int a=lane, b=m>>8, pos=m&255, i=pos>>4, j=pos&15;
    float cls = hs[w][a] + cls_b[a];
    float r0 = hs[w][9+a*4+0]+reg_b[a*4+0], r1 = hs[w][9+a*4+1]+reg_b[a*4+1];
    float r2 = hs[w][9+a*4+2]+reg_b[a*4+2], r3 = hs[w][9+a*4+3]+reg_b[a*4+3];
    const double scl[3]={8.0,16.0,32.0}, rat[3]={0.5,1.0,2.0};
    double s=scl[a/3], rr=rat[a-(a/3)*3];
    double wD=s*sqrt(rr), hD=s/sqrt(rr);
    double xcD=(j+0.5)*16.0, ycD=(i+0.5)*16.0;
    float ax1=(float)(xcD-wD*0.5), ay1=(float)(ycD-hD*0.5);
    float ax2=(float)(xcD+wD*0.5), ay2=(float)(ycD+hD*0.5);
    float aw=ax2-ax1, ah=ay2-ay1, ctx=ax1+0.5f*aw, cty=ay1+0.5f*ah;
    float cx=r0*aw+ctx, cy=r1*ah+cty;
    float pw=expf(r2)*aw, ph=expf(r3)*ah;
    float x1=fminf(fmaxf(cx-0.5f*pw,0.f),256.f), y1=fminf(fmaxf(cy-0.5f*ph,0.f),256.f);
    float x2=fminf(fmaxf(cx+0.5f*pw,0.f),256.f), y2=fminf(fmaxf(cy+0.5f*ph,0.f),256.f);
    if (x2-x1<1.f) x2=x1+1.f;
    if (y2-y1<1.f) y2=y1+1.f;
    int aidx = pos*9+a;
    g_scores[b*2304+aidx] = 1.f/(1.f+expf(-cls));
    float* bp = &g_boxes[((size_t)b*2304+aidx)*4];
    bp[0]=x1; bp[1]=y1; bp[2]=x2; bp[3]=y2;
  }
}

// 5. stable top-30 per image (selection, lower-index tie-break = lax.top_k)
__global__ void topk_kernel() {
  int b = blockIdx.x, tid = threadIdx.x;
  __shared__ unsigned sel[72];
  __shared__ float sv[256]; __shared__ int si[256];
  if (tid<72) sel[tid]=0u;
  __syncthreads();
  const float* sc = g_scores + (size_t)b*2304;
  for (int k=0;k<KTOP;k++) {
    float bv=-1e30f; int bi=1<<30;
    for (int e=tid;e<2304;e+=256) {
      if (sel[e>>5] & (1u<<(e&31))) continue;
      float v=sc[e];
      if (v>bv || (v==bv && e<bi)) { bv=v; bi=e; }
    }
    sv[tid]=bv; si[tid]=bi; __syncthreads();
    for (int off=128;off>0;off>>=1) {
      if (tid<off) {
        float v2=sv[tid+off]; int i2=si[tid+off];
        if (v2>sv[tid] || (v2==sv[tid] && i2<si[tid])) { sv[tid]=v2; si[tid]=i2; }
      }
      __syncthreads();
    }
    if (tid==0) {
      int best=si[0];
      sel[best>>5] |= (1u<<(best&31));
      const float* bp=&g_boxes[((size_t)b*2304+best)*4];
      float* rp=&g_rois[(b*KTOP+k)*4];
      rp[0]=bp[0]; rp[1]=bp[1]; rp[2]=bp[2]; rp[3]=bp[3];
    }
    __syncthreads();
  }
}

// 6. greedy NMS, exact reference semantics
__global__ void nms_kernel() {
  int b=blockIdx.x, t=threadIdx.x;
  __shared__ float x1s[30],y1s[30],x2s[30],y2s[30],ars[30];
  __shared__ int keep[30];
  if (t<30) {
    const float* rp=&g_rois[(b*KTOP+t)*4];
    x1s[t]=rp[0]; y1s[t]=rp[1]; x2s[t]=rp[2]; y2s[t]=rp[3];
    ars[t]=(rp[2]-rp[0])*(rp[3]-rp[1]); keep[t]=1;
  }
  __syncwarp();
  for (int i=0;i<KTOP;i++) {
    if (t<30 && t>i && keep[i]) {
      float iw=fmaxf(fminf(x2s[i],x2s[t])-fmaxf(x1s[i],x1s[t]),0.f);
      float ih=fmaxf(fminf(y2s[i],y2s[t])-fmaxf(y1s[i],y1s[t]),0.f);
      float inter=iw*ih;
      if (inter/(ars[i]+ars[t]-inter) > 0.85f) keep[t]=0;
    }
    __syncwarp();
  }
  if (t<30) g_valid[b*KTOP+t]=keep[t];
}

// 7. integral images (rows then cols), exact fp32 (0/1 values)
__global__ void integral_rows_kernel(const float* __restrict__ gt) {
  int b=blockIdx.x, t=threadIdx.x;
  float* I = g_I + (size_t)b*66049;
  I[t]=0.f; if (t==0) I[256]=0.f;
  const float* g = gt + (size_t)b*65536 + (size_t)t*256;
  float* row = I + (size_t)(t+1)*257;
  row[0]=0.f; float run=0.f;
  for (int x=0;x<256;x++){ run+=g[x]; row[x+1]=run; }
}
__global__ void integral_cols_kernel() {
  int b=blockIdx.x, x=threadIdx.x+1;
  float* I = g_I + (size_t)b*66049;
  float run=0.f;
  for (int y=1;y<=256;y++){ run += I[(size_t)y*257+x]; I[(size_t)y*257+x]=run; }
}

// 8. ROI labels
__global__ void labels_kernel() {
  int r = blockIdx.x*blockDim.x + threadIdx.x;
  if (r>=NROI) return;
  int b = r/KTOP;
  const float* roi=&g_rois[r*4];
  int x1=min(max((int)roi[0],0),256), y1=min(max((int)roi[1],0),256);
  int x2=min(max((int)roi[2],0),256), y2=min(max((int)roi[3],0),256);
  const float* I = g_I + (size_t)b*66049;
  float s = I[(size_t)y2*257+x2]-I[(size_t)y1*257+x2]-I[(size_t)y2*257+x1]+I[(size_t)y1*257+x1];
  int cnt=(y2-y1)*(x2-x1);
  g_labels[r] = (cnt>0) ? ((s/(float)max(cnt,1))>0.5f ? 1 : 0) : 0;
}

// 9. ROI align 7x7 bilinear mean over 1024 channels
__global__ void roi_align_kernel() {
  int r=blockIdx.x, t=threadIdx.x, b=r/KTOP;
  __shared__ float w00[49],w01[49],w10[49],w11[49];
  __shared__ int o00[49],o01[49],o10[49],o11[49],pok[49];
  if (t<49) {
    const float* roi=&g_rois[r*4];
    const float sc=1.f/16.f;
    float x1=roi[0]*sc, y1=roi[1]*sc;
    float rw=fmaxf(roi[2]*sc-x1,1.f), rh=fmaxf(roi[3]*sc-y1,1.f);
    int p=t/7, q=t-p*7;
    float X=x1+(q+0.5f)*(rw/7.f), Y=y1+(p+0.5f)*(rh/7.f);
    int ok = (Y>-1.f)&&(Y<16.f)&&(X>-1.f)&&(X<16.f);
    float Xc=fminf(fmaxf(X,0.f),15.f), Yc=fminf(fmaxf(Y,0.f),15.f);
    int x0=(int)floorf(Xc), y0=(int)floorf(Yc);
    int x1i=min(x0+1,15), y1i=min(y0+1,15);
    float lx=Xc-(float)x0, ly=Yc-(float)y0, hx=1.f-lx, hy=1.f-ly;
    w00[t]=hy*hx; w01[t]=hy*lx; w10[t]=ly*hx; w11[t]=ly*lx;
    o00[t]=(y0*16+x0)*CDIM; o01[t]=(y0*16+x1i)*CDIM;
    o10[t]=(y1i*16+x0)*CDIM; o11[t]=(y1i*16+x1i)*CDIM;
    pok[t]=ok;
  }
  __syncthreads();
  const float* Sb = g_S + (size_t)b*NPOS*CDIM;
  float a0=0,a1=0,a2=0,a3=0;
  for (int pt=0;pt<49;pt++) {
    if (!pok[pt]) continue;
    const float *p00=Sb+o00[pt],*p01=Sb+o01[pt],*p10=Sb+o10[pt],*p11=Sb+o11[pt];
    float W00=w00[pt],W01=w01[pt],W10=w10[pt],W11=w11[pt];
    a0 += W00*p00[t]     + W01*p01[t]     + W10*p10[t]     + W11*p11[t];
    a1 += W00*p00[t+256] + W01*p01[t+256] + W10*p10[t+256] + W11*p11[t+256];
    a2 += W00*p00[t+512] + W01*p01[t+512] + W10*p10[t+512] + W11*p11[t+512];
    a3 += W00*p00[t+768] + W01*p01[t+768] + W10*p10[t+768] + W11*p11[t+768];
  }
  float* out = g_pooled + (size_t)r*CDIM;
  out[t]=a0/49.f; out[t+256]=a1/49.f; out[t+512]=a2/49.f; out[t+768]=a3/49.f;
}

// 10. C = A*B^T + bias (optional relu). mode0: pooled(960,1024)->h; mode1: h(960,256)->proj
__global__ __launch_bounds__(256) void gemm_abt_kernel(const float* __restrict__ Bm,
                                                       const float* __restrict__ bias,
                                                       int mode, int K, int relu) {
  const float* A = (mode==0) ? g_pooled : g_h;
  float* C = (mode==0) ? g_h : g_proj;
  const int N=256;
  const int bm = blockIdx.y*64, bn = blockIdx.x*64, tid = threadIdx.x;
  __shared__ float As[16][68];
  __shared__ float Bs[16][68];
  const int lr = tid>>2, lk = (tid&3)<<2;
  const int tm = (tid>>4)<<2, tn = (tid&15)<<2;
  float acc[4][4];
#pragma unroll
  for (int r=0;r<4;r++)
#pragma unroll
    for (int c=0;c<4;c++) acc[r][c]=0.f;
  for (int k0=0;k0<K;k0+=16) {
    float4 a4 = *(const float4*)&A[(size_t)(bm+lr)*K + k0+lk];
    float4 b4 = *(const float4*)&Bm[(size_t)(bn+lr)*K + k0+lk];
    __syncthreads();
    As[lk+0][lr]=a4.x; As[lk+1][lr]=a4.y; As[lk+2][lr]=a4.z; As[lk+3][lr]=a4.w;
    Bs[lk+0][lr]=b4.x; Bs[lk+1][lr]=b4.y; Bs[lk+2][lr]=b4.z; Bs[lk+3][lr]=b4.w;
    __syncthreads();
#pragma unroll
    for (int kk=0;kk<16;kk++) {
      float4 av=*(const float4*)&As[kk][tm];
      float4 bv=*(const float4*)&Bs[kk][tn];
      float aa[4]={av.x,av.y,av.z,av.w}, bb[4]={bv.x,bv.y,bv.z,bv.w};
#pragma unroll
      for (int r=0;r<4;r++)
#pragma unroll
        for (int c=0;c<4;c++) acc[r][c]+=aa[r]*bb[c];
    }
  }
#pragma unroll
  for (int r=0;r<4;r++) {
    size_t off=(size_t)(bm+tm+r)*N + bn+tn;
#pragma unroll
    for (int c=0;c<4;c++) {
      float v=acc[r][c]+bias[bn+tn+c];
      if (relu) v=fmaxf(v,0.f);
      C[off+c]=v;
    }
  }
}

// 11. row L2 normalize
__global__ void normalize_kernel() {
  int i=blockIdx.x, t=threadIdx.x;
  float v = g_proj[(size_t)i*PROJD+t];
  __shared__ float red[256];
  red[t]=v*v; __syncthreads();
  for (int off=128;off>0;off>>=1){ if (t<off) red[t]+=red[t+off]; __syncthreads(); }
  float nrm = fmaxf(sqrtf(red[0]), 1e-12f);
  g_nf[(size_t)i*PROJD+t] = v/nrm;
}

// 12. SupCon per-row
__global__ void supcon_kernel() {
  int i=blockIdx.x, t=threadIdx.x;
  __shared__ float nfi[256];
  __shared__ float rp[256], ra[256]; __shared__ int rc[256];
  nfi[t] = g_nf[(size_t)i*PROJD+t];
  __syncthreads();
  int li=g_labels[i], vi=g_valid[i];
  float psum=0.f, asum=0.f; int pcnt=0;
  for (int j=t;j<NROI;j+=256) {
    const float* nj = g_nf + (size_t)j*PROJD;
    float dot=0.f;
#pragma unroll 8
    for (int c=0;c<256;c++) dot += nfi[c]*nj[c];
    float es = expf(dot*(1.f/0.07f));
    int vj=g_valid[j];
    int nd = (j!=i), vv = vi && vj;
    int isp = (g_labels[j]==li) && nd && vv;
    int ism = nd && vv;
    if (isp) { psum+=es; pcnt++; }
    if (ism) asum+=es;
  }
  rp[t]=psum; ra[t]=asum; rc[t]=pcnt; __syncthreads();
  for (int off=128;off>0;off>>=1) {
    if (t<off){ rp[t]+=rp[t+off]; ra[t]+=ra[t+off]; rc[t]+=rc[t+off]; }
    __syncthreads();
  }
  if (t==0) {
    float ratio = rp[0]/(ra[0]+1e-12f);
    float l = -logf(ratio+1e-12f);
    int active = vi && (rc[0]>0);
    g_rowl[i] = active ? l : 0.f;
    g_rowact[i] = active;
  }
}

// 13. final reduce -> scalar loss
__global__ void finalize_kernel(float* out) {
  int t=threadIdx.x;
  __shared__ float rl[256]; __shared__ int rc[256];
  float s=0.f; int c=0;
  for (int i=t;i<NROI;i+=256){ s+=g_rowl[i]; c+=g_rowact[i]; }
  rl[t]=s; rc[t]=c; __syncthreads();
  for (int off=128;off>0;off>>=1){ if (t<off){ rl[t]+=rl[t+off]; rc[t]+=rc[t+off]; } __syncthreads(); }
  if (t==0) out[0] = (rc[0]>0) ? rl[0]/(float)max(rc[0],1) : 0.f;
}

extern "C" void kernel_launch(void* const* d_in, const int* in_sizes, int n_in,
                              void* d_out, int out_size) {
  const float* clip   = (const float*)d_in[0];
  const float* gt     = (const float*)d_in[1];
  const float* conv_w = (const float*)d_in[2];
  const float* conv_b = (const float*)d_in[3];
  const float* cls_w  = (const float*)d_in[4];
  const float* cls_b  = (const float*)d_in[5];
  const float* reg_w  = (const float*)d_in[6];
  const float* reg_b  = (const float*)d_in[7];
  const float* pw1    = (const float*)d_in[8];
  const float* pb1    = (const float*)d_in[9];
  const float* pw2    = (const float*)d_in[10];
  const float* pb2    = (const float*)d_in[11];

  build_spatial_kernel<<<MROWS, 256>>>(clip);
  transpose_w_kernel<<<(OC*CDIM)/256, 256>>>(conv_w);
  conv_gemm_kernel<<<dim3(4,64), 256>>>(conv_b);
  heads_kernel<<<MROWS/8, 256>>>(cls_w, cls_b, reg_w, reg_b);
  topk_kernel<<<NB, 256>>>();
  nms_kernel<<<NB, 32>>>();
  integral_rows_kernel<<<NB, 256>>>(gt);
  integral_cols_kernel<<<NB, 256>>>();
  labels_kernel<<<(NROI+255)/256, 256>>>();
  roi_align_kernel<<<NROI, 256>>>();
  gemm_abt_kernel<<<dim3(4,15), 256>>>(pw1, pb1, 0, CDIM, 1);
  gemm_abt_kernel<<<dim3(4,15), 256>>>(pw2, pb2, 1, PROJD, 0);
  normalize_kernel<<<NROI, 256>>>();
  supcon_kernel<<<NROI, 256>>>();
  finalize_kernel<<<1, 256>>>((float*)d_out);
}

// round 10
// speedup vs baseline: 1.2071x; 1.2071x over previous
#include <cuda_runtime.h>
#include <cuda_bf16.h>
#include <math.h>
#include <stdint.h>

#define NB 32
#define CDIM 1024
#define FE 16
#define NANC 9
#define KTOP 30
#define NROI (NB*KTOP)
#define PROJD 256
#define OC 512
#define NPOS (FE*FE)
#define MROWS (NB*NPOS)

__device__ float g_S[MROWS*CDIM];
__device__ float g_X[MROWS*OC];
__device__ float g_scores[NB*NPOS*NANC];
__device__ float g_boxes[NB*NPOS*NANC*4];
__device__ float g_rois[NROI*4];
__device__ int   g_valid[NROI];
__device__ float g_I[NB*257*257];
__device__ float g_pooled[NROI*CDIM];
__device__ float g_h[NROI*PROJD];
__device__ float g_proj[NROI*PROJD];
__device__ float g_nf[NROI*PROJD];
__device__ int   g_labels[NROI];
__device__ float g_rowl[NROI];
__device__ int   g_rowact[NROI];

// bf16 3-way splits: A spatial [m][c], B weights [tap][o][c]
__device__ __align__(16) __nv_bfloat16 gA0[MROWS*CDIM];
__device__ __align__(16) __nv_bfloat16 gA1[MROWS*CDIM];
__device__ __align__(16) __nv_bfloat16 gA2[MROWS*CDIM];
__device__ __align__(16) __nv_bfloat16 gB0[9*OC*CDIM];
__device__ __align__(16) __nv_bfloat16 gB1[9*OC*CDIM];
__device__ __align__(16) __nv_bfloat16 gB2[9*OC*CDIM];

__device__ __forceinline__ uint32_t smem_u32(const void* p) {
  uint32_t a;
  asm("{ .reg .u64 t; cvta.to.shared.u64 t, %1; cvt.u32.u64 %0, t; }" : "=r"(a) : "l"(p));
  return a;
}

// 1. spatial: clip[1+p][b][c] -> g_S (fp32) + 3-way bf16 split
__global__ void build_split_spatial(const float* __restrict__ clip) {
  int bx = blockIdx.x; int b = bx >> 8, p = bx & 255;
  const float* src = clip + (size_t)(1+p)*NB*CDIM + (size_t)b*CDIM;
#pragma unroll
  for (int q = 0; q < 4; q++) {
    int c = threadIdx.x + q*256;
    float v = src[c];
    size_t di = (size_t)bx*CDIM + c;
    g_S[di] = v;
    __nv_bfloat16 h = __float2bfloat16(v);
    float r1 = v - __bfloat162float(h);
    __nv_bfloat16 m = __float2bfloat16(r1);
    float r2 = r1 - __bfloat162float(m);
    gA0[di] = h; gA1[di] = m; gA2[di] = __float2bfloat16(r2);
  }
}

// 2. weights conv_w[o][c][t] -> gB{0,1,2}[t][o][c]
__global__ void split_w_kernel(const float* __restrict__ conv_w) {
  int e = blockIdx.x*256 + threadIdx.x; // o*1024+c
  int o = e >> 10, c = e & 1023;
  const float* src = conv_w + (size_t)e*9;
#pragma unroll
  for (int t = 0; t < 9; t++) {
    float v = src[t];
    __nv_bfloat16 h = __float2bfloat16(v);
    float r1 = v - __bfloat162float(h);
    __nv_bfloat16 m = __float2bfloat16(r1);
    float r2 = r1 - __bfloat162float(m);
    size_t di = ((size_t)t*OC + o)*CDIM + c;
    gB0[di] = h; gB1[di] = m; gB2[di] = __float2bfloat16(r2);
  }
}

// 3. conv 3x3 via mma.sync bf16 (HMMA), 3-split x 6 products, fp32 acc.
//    CTA 128x128, 8 warps (2x4), warp tile 64x32, k-step 16, 576 stages.
#define ASTRIDE 48
#define SPL_SZ (128*ASTRIDE)
#define STAGE_SZ (6*SPL_SZ)
#define CONV_SMEM (2*STAGE_SZ)

#define CPA16(dst, src, sz) \
  asm volatile("cp.async.cg.shared.global [%0], [%1], 16, %2;" :: "r"(dst), "l"(src), "r"(sz))
#define LDSM4(r0,r1,r2,r3,addr) \
  asm volatile("ldmatrix.sync.aligned.m8n8.x4.shared.b16 {%0,%1,%2,%3}, [%4];" \
    : "=r"(r0),"=r"(r1),"=r"(r2),"=r"(r3) : "r"(addr))
#define MMA16816(d0,d1,d2,d3,a0,a1,a2,a3,b0,b1) \
  asm volatile("mma.sync.aligned.m16n8k16.row.col.f32.bf16.bf16.f32 " \
    "{%0,%1,%2,%3}, {%4,%5,%6,%7}, {%8,%9}, {%0,%1,%2,%3};" \
    : "+f"(d0),"+f"(d1),"+f"(d2),"+f"(d3) \
    : "r"(a0),"r"(a1),"r"(a2),"r"(a3),"r"(b0),"r"(b1))

__global__ void __launch_bounds__(256, 1) conv_mma_kernel(const float* __restrict__ convb) {
  extern __shared__ __align__(128) char smem[];
  uint32_t sb = smem_u32(smem);
  const int tid = threadIdx.x, wid = tid >> 5, lane = tid & 31;
  const int bn = blockIdx.x*128, bm = blockIdx.y*128;
  const int wm = (wid >> 2)*64, wn = (wid & 3)*32;

  const int lrow = tid >> 1, lchunk = tid & 1;
  const int am = bm + lrow;
  const int ab = am >> 8, apos = am & 255, api = apos >> 4, apj = apos & 15;

  float acc[4][4][4];
#pragma unroll
  for (int i = 0; i < 4; i++)
#pragma unroll
    for (int j = 0; j < 4; j++)
#pragma unroll
      for (int k = 0; k < 4; k++) acc[i][j][k] = 0.f;

  const __nv_bfloat16* gAp[3] = {gA0, gA1, gA2};
  const __nv_bfloat16* gBp[3] = {gB0, gB1, gB2};

  auto issue = [&](int s) {
    uint32_t dst = sb + (uint32_t)(s & 1)*STAGE_SZ;
    int tap = s >> 6, kc = s & 63;
    int di = tap/3 - 1, dj = tap - (tap/3)*3 - 1;
    int ii = api + di, jj = apj + dj;
    bool ok = ((unsigned)ii < 16u) && ((unsigned)jj < 16u);
    size_t asrc = ok ? ((size_t)((ab<<8)+(ii<<4)+jj))*CDIM + kc*16 + lchunk*8 : 0;
    int asz = ok ? 16 : 0;
    uint32_t adst = dst + lrow*ASTRIDE + lchunk*16;
    CPA16(adst + 0*SPL_SZ, gAp[0] + asrc, asz);
    CPA16(adst + 1*SPL_SZ, gAp[1] + asrc, asz);
    CPA16(adst + 2*SPL_SZ, gAp[2] + asrc, asz);
    size_t bsrc = ((size_t)tap*OC + bn + lrow)*CDIM + kc*16 + lchunk*8;
    uint32_t bdst = dst + 3*SPL_SZ + lrow*ASTRIDE + lchunk*16;
    CPA16(bdst + 0*SPL_SZ, gBp[0] + bsrc, 16);
    CPA16(bdst + 1*SPL_SZ, gBp[1] + bsrc, 16);
    CPA16(bdst + 2*SPL_SZ, gBp[2] + bsrc, 16);
    asm volatile("cp.async.commit_group;" ::: "memory");
  };

  issue(0);
  issue(1);

  // precomputed intra-warp ldmatrix offsets (within a split block)
  const uint32_t a_off = (uint32_t)(wm + (lane & 15))*ASTRIDE + (uint32_t)(lane >> 4)*16;
  const uint32_t b_off = (uint32_t)(wn + (lane & 7) + ((lane >> 4) << 3))*ASTRIDE
                       + (uint32_t)((lane >> 3) & 1)*16;

  for (int s = 0; s < 576; s++) {
    asm volatile("cp.async.wait_group 1;" ::: "memory");
    __syncthreads();
    uint32_t base = sb + (uint32_t)(s & 1)*STAGE_SZ;

    uint32_t Ar[3][4][4];
    uint32_t Br[3][4][2];
#pragma unroll
    for (int p = 0; p < 3; p++) {
#pragma unroll
      for (int i = 0; i < 4; i++) {
        uint32_t ad = base + p*SPL_SZ + a_off + (uint32_t)(i*16)*ASTRIDE;
        LDSM4(Ar[p][i][0], Ar[p][i][1], Ar[p][i][2], Ar[p][i][3], ad);
      }
#pragma unroll
      for (int j = 0; j < 2; j++) {
        uint32_t bd = base + (3+p)*SPL_SZ + b_off + (uint32_t)(j*16)*ASTRIDE;
        LDSM4(Br[p][2*j][0], Br[p][2*j][1], Br[p][2*j+1][0], Br[p][2*j+1][1], bd);
      }
    }
    __syncthreads();
    if (s + 2 < 576) issue(s + 2);
    else asm volatile("cp.async.commit_group;" ::: "memory");

    const int pa[6] = {0,0,1,0,1,2};
    const int pb[6] = {0,1,0,2,1,0};
#pragma unroll
    for (int c6 = 0; c6 < 6; c6++) {
#pragma unroll
      for (int i = 0; i < 4; i++)
#pragma unroll
        for (int jn = 0; jn < 4; jn++)
          MMA16816(acc[i][jn][0], acc[i][jn][1], acc[i][jn][2], acc[i][jn][3],
                   Ar[pa[c6]][i][0], Ar[pa[c6]][i][1], Ar[pa[c6]][i][2], Ar[pa[c6]][i][3],
                   Br[pb[c6]][jn][0], Br[pb[c6]][jn][1]);
    }
  }

  const int gi = lane >> 2, t4 = lane & 3;
#pragma unroll
  for (int i = 0; i < 4; i++) {
#pragma unroll
    for (int jn = 0; jn < 4; jn++) {
      int r0 = bm + wm + i*16 + gi;
      int c0 = bn + wn + jn*8 + t4*2;
      float b0v = convb[c0], b1v = convb[c0+1];
      g_X[(size_t)r0*OC + c0]       = fmaxf(acc[i][jn][0] + b0v, 0.f);
      g_X[(size_t)r0*OC + c0 + 1]   = fmaxf(acc[i][jn][1] + b1v, 0.f);
      g_X[(size_t)(r0+8)*OC + c0]     = fmaxf(acc[i][jn][2] + b0v, 0.f);
      g_X[(size_t)(r0+8)*OC + c0 + 1] = fmaxf(acc[i][jn][3] + b1v, 0.f);
    }
  }
}

// 4. heads + anchor decode + sigmoid. One warp per position.
__global__ void heads_kernel(const float* __restrict__ cls_w, const float* __restrict__ cls_b,
                             const float* __restrict__ reg_w, const float* __restrict__ reg_b) {
  int w = threadIdx.x>>5, lane = threadIdx.x&31;
  int m = blockIdx.x*8 + w;
  float ac[9], ar[36];
#pragma unroll
  for (int a=0;a<9;a++) ac[a]=0.f;
#pragma unroll
  for (int a=0;a<36;a++) ar[a]=0.f;
  const float* xr = g_X + (size_t)m*OC;
  for (int c=lane;c<OC;c+=32) {
    float xv = xr[c];
#pragma unroll
    for (int a=0;a<9;a++) ac[a] += xv*cls_w[a*OC+c];
#pragma unroll
    for (int a=0;a<36;a++) ar[a] += xv*reg_w[a*OC+c];
  }
  __shared__ float hs[8][46];
#pragma unroll
  for (int a=0;a<9;a++){ float v=ac[a];
    for (int o=16;o>0;o>>=1) v += __shfl_xor_sync(0xffffffffu,v,o);
    if (lane==0) hs[w][a]=v; }
#pragma unroll
  for (int a=0;a<36;a++){ float v=ar[a];
    for (int o=16;o>0;o>>=1) v += __shfl_xor_sync(0xffffffffu,v,o);
    if (lane==0) hs[w][9+a]=v; }
  __syncwarp();
  if (lane<9) {
    int a=lane, b=m>>8, pos=m&255, i=pos>>4, j=pos&15;
    float cls = hs[w][a] + cls_b[a];
    float r0 = hs[w][9+a*4+0]+reg_b[a*4+0], r1 = hs[w][9+a*4+1]+reg_b[a*4+1];
    float r2 = hs[w][9+a*4+2]+reg_b[a*4+2], r3 = hs[w][9+a*4+3]+reg_b[a*4+3];
    const double scl[3]={8.0,16.0,32.0}, rat[3]={0.5,1.0,2.0};
    double s=scl[a/3], rr=rat[a-(a/3)*3];
    double wD=s*sqrt(rr), hD=s/sqrt(rr);
    double xcD=(j+0.5)*16.0, ycD=(i+0.5)*16.0;
    float ax1=(float)(xcD-wD*0.5), ay1=(float)(ycD-hD*0.5);
    float ax2=(float)(xcD+wD*0.5), ay2=(float)(ycD+hD*0.5);
    float aw=ax2-ax1, ah=ay2-ay1, ctx=ax1+0.5f*aw, cty=ay1+0.5f*ah;
    float cx=r0*aw+ctx, cy=r1*ah+cty;
    float pw=expf(r2)*aw, ph=expf(r3)*ah;
    float x1=fminf(fmaxf(cx-0.5f*pw,0.f),256.f), y1=fminf(fmaxf(cy-0.5f*ph,0.f),256.f);
    float x2=fminf(fmaxf(cx+0.5f*pw,0.f),256.f), y2=fminf(fmaxf(cy+0.5f*ph,0.f),256.f);
    if (x2-x1<1.f) x2=x1+1.f;
    if (y2-y1<1.f) y2=y1+1.f;
    int aidx = pos*9+a;
    g_scores[b*2304+aidx] = 1.f/(1.f+expf(-cls));
    float* bp = &g_boxes[((size_t)b*2304+aidx)*4];
    bp[0]=x1; bp[1]=y1; bp[2]=x2; bp[3]=y2;
  }
}

// 5. stable top-30 per image
__global__ void topk_kernel() {
  int b = blockIdx.x, tid = threadIdx.x;
  __shared__ unsigned sel[72];
  __shared__ float sv[256]; __shared__ int si[256];
  if (tid<72) sel[tid]=0u;
  __syncthreads();
  const float* sc = g_scores + (size_t)b*2304;
  for (int k=0;k<KTOP;k++) {
    float bv=-1e30f; int bi=1<<30;
    for (int e=tid;e<2304;e+=256) {
      if (sel[e>>5] & (1u<<(e&31))) continue;
      float v=sc[e];
      if (v>bv || (v==bv && e<bi)) { bv=v; bi=e; }
    }
    sv[tid]=bv; si[tid]=bi; __syncthreads();
    for (int off=128;off>0;off>>=1) {
      if (tid<off) {
        float v2=sv[tid+off]; int i2=si[tid+off];
        if (v2>sv[tid] || (v2==sv[tid] && i2<si[tid])) { sv[tid]=v2; si[tid]=i2; }
      }
      __syncthreads();
    }
    if (tid==0) {
      int best=si[0];
      sel[best>>5] |= (1u<<(best&31));
      const float* bp=&g_boxes[((size_t)b*2304+best)*4];
      float* rp=&g_rois[(b*KTOP+k)*4];
      rp[0]=bp[0]; rp[1]=bp[1]; rp[2]=bp[2]; rp[3]=bp[3];
    }
    __syncthreads();
  }
}

// 6. greedy NMS
__global__ void nms_kernel() {
  int b=blockIdx.x, t=threadIdx.x;
  __shared__ float x1s[30],y1s[30],x2s[30],y2s[30],ars[30];
  __shared__ int keep[30];
  if (t<30) {
    const float* rp=&g_rois[(b*KTOP+t)*4];
    x1s[t]=rp[0]; y1s[t]=rp[1]; x2s[t]=rp[2]; y2s[t]=rp[3];
    ars[t]=(rp[2]-rp[0])*(rp[3]-rp[1]); keep[t]=1;
  }
  __syncwarp();
  for (int i=0;i<KTOP;i++) {
    if (t<30 && t>i && keep[i]) {
      float iw=fmaxf(fminf(x2s[i],x2s[t])-fmaxf(x1s[i],x1s[t]),0.f);
      float ih=fmaxf(fminf(y2s[i],y2s[t])-fmaxf(y1s[i],y1s[t]),0.f);
      float inter=iw*ih;
      if (inter/(ars[i]+ars[t]-inter) > 0.85f) keep[t]=0;
    }
    __syncwarp();
  }
  if (t<30) g_valid[b*KTOP+t]=keep[t];
}

// 7. integral images
__global__ void integral_rows_kernel(const float* __restrict__ gt) {
  int b=blockIdx.x, t=threadIdx.x;
  float* I = g_I + (size_t)b*66049;
  I[t]=0.f; if (t==0) I[256]=0.f;
  const float* g = gt + (size_t)b*65536 + (size_t)t*256;
  float* row = I + (size_t)(t+1)*257;
  row[0]=0.f; float run=0.f;
  for (int x=0;x<256;x++){ run+=g[x]; row[x+1]=run; }
}
__global__ void integral_cols_kernel() {
  int b=blockIdx.x, x=threadIdx.x+1;
  float* I = g_I + (size_t)b*66049;
  float run=0.f;
  for (int y=1;y<=256;y++){ run += I[(size_t)y*257+x]; I[(size_t)y*257+x]=run; }
}

// 8. ROI labels
__global__ void labels_kernel() {
  int r = blockIdx.x*blockDim.x + threadIdx.x;
  if (r>=NROI) return;
  int b = r/KTOP;
  const float* roi=&g_rois[r*4];
  int x1=min(max((int)roi[0],0),256), y1=min(max((int)roi[1],0),256);
  int x2=min(max((int)roi[2],0),256), y2=min(max((int)roi[3],0),256);
  const float* I = g_I + (size_t)b*66049;
  float s = I[(size_t)y2*257+x2]-I[(size_t)y1*257+x2]-I[(size_t)y2*257+x1]+I[(size_t)y1*257+x1];
  int cnt=(y2-y1)*(x2-x1);
  g_labels[r] = (cnt>0) ? ((s/(float)max(cnt,1))>0.5f ? 1 : 0) : 0;
}

// 9. ROI align
__global__ void roi_align_kernel() {
  int r=blockIdx.x, t=threadIdx.x, b=r/KTOP;
  __shared__ float w00[49],w01[49],w10[49],w11[49];
  __shared__ int o00[49],o01[49],o10[49],o11[49],pok[49];
  if (t<49) {
    const float* roi=&g_rois[r*4];
    const float sc=1.f/16.f;
    float x1=roi[0]*sc, y1=roi[1]*sc;
    float rw=fmaxf(roi[2]*sc-x1,1.f), rh=fmaxf(roi[3]*sc-y1,1.f);
    int p=t/7, q=t-p*7;
    float X=x1+(q+0.5f)*(rw/7.f), Y=y1+(p+0.5f)*(rh/7.f);
    int ok = (Y>-1.f)&&(Y<16.f)&&(X>-1.f)&&(X<16.f);
    float Xc=fminf(fmaxf(X,0.f),15.f), Yc=fminf(fmaxf(Y,0.f),15.f);
    int x0=(int)floorf(Xc), y0=(int)floorf(Yc);
    int x1i=min(x0+1,15), y1i=min(y0+1,15);
    float lx=Xc-(float)x0, ly=Yc-(float)y0, hx=1.f-lx, hy=1.f-ly;
    w00[t]=hy*hx; w01[t]=hy*lx; w10[t]=ly*hx; w11[t]=ly*lx;
    o00[t]=(y0*16+x0)*CDIM; o01[t]=(y0*16+x1i)*CDIM;
    o10[t]=(y1i*16+x0)*CDIM; o11[t]=(y1i*16+x1i)*CDIM;
    pok[t]=ok;
  }
  __syncthreads();
  const float* Sb = g_S + (size_t)b*NPOS*CDIM;
  float a0=0,a1=0,a2=0,a3=0;
  for (int pt=0;pt<49;pt++) {
    if (!pok[pt]) continue;
    const float *p00=Sb+o00[pt],*p01=Sb+o01[pt],*p10=Sb+o10[pt],*p11=Sb+o11[pt];
    float W00=w00[pt],W01=w01[pt],W10=w10[pt],W11=w11[pt];
    a0 += W00*p00[t]     + W01*p01[t]     + W10*p10[t]     + W11*p11[t];
    a1 += W00*p00[t+256] + W01*p01[t+256] + W10*p10[t+256] + W11*p11[t+256];
    a2 += W00*p00[t+512] + W01*p01[t+512] + W10*p10[t+512] + W11*p11[t+512];
    a3 += W00*p00[t+768] + W01*p01[t+768] + W10*p10[t+768] + W11*p11[t+768];
  }
  float* out = g_pooled + (size_t)r*CDIM;
  out[t]=a0/49.f; out[t+256]=a1/49.f; out[t+512]=a2/49.f; out[t+768]=a3/49.f;
}

// 10. C = A*B^T + bias
__global__ __launch_bounds__(256) void gemm_abt_kernel(const float* __restrict__ Bm,
                                                       const float* __restrict__ bias,
                                                       int mode, int K, int relu) {
  const float* A = (mode==0) ? g_pooled : g_h;
  float* C = (mode==0) ? g_h : g_proj;
  const int N=256;
  const int bm = blockIdx.y*64, bn = blockIdx.x*64, tid = threadIdx.x;
  __shared__ float As[16][68];
  __shared__ float Bs[16][68];
  const int lr = tid>>2, lk = (tid&3)<<2;
  const int tm = (tid>>4)<<2, tn = (tid&15)<<2;
  float acc[4][4];
#pragma unroll
  for (int r=0;r<4;r++)
#pragma unroll
    for (int c=0;c<4;c++) acc[r][c]=0.f;
  for (int k0=0;k0<K;k0+=16) {
    float4 a4 = *(const float4*)&A[(size_t)(bm+lr)*K + k0+lk];
    float4 b4 = *(const float4*)&Bm[(size_t)(bn+lr)*K + k0+lk];
    __syncthreads();
    As[lk+0][lr]=a4.x; As[lk+1][lr]=a4.y; As[lk+2][lr]=a4.z; As[lk+3][lr]=a4.w;
    Bs[lk+0][lr]=b4.x; Bs[lk+1][lr]=b4.y; Bs[lk+2][lr]=b4.z; Bs[lk+3][lr]=b4.w;
    __syncthreads();
#pragma unroll
    for (int kk=0;kk<16;kk++) {
      float4 av=*(const float4*)&As[kk][tm];
      float4 bv=*(const float4*)&Bs[kk][tn];
      float aa[4]={av.x,av.y,av.z,av.w}, bb[4]={bv.x,bv.y,bv.z,bv.w};
#pragma unroll
      for (int r=0;r<4;r++)
#pragma unroll
        for (int c=0;c<4;c++) acc[r][c]+=aa[r]*bb[c];
    }
  }
#pragma unroll
  for (int r=0;r<4;r++) {
    size_t off=(size_t)(bm+tm+r)*N + bn+tn;
#pragma unroll
    for (int c=0;c<4;c++) {
      float v=acc[r][c]+bias[bn+tn+c];
      if (relu) v=fmaxf(v,0.f);
      C[off+c]=v;
    }
  }
}

// 11. row L2 normalize
__global__ void normalize_kernel() {
  int i=blockIdx.x, t=threadIdx.x;
  float v = g_proj[(size_t)i*PROJD+t];
  __shared__ float red[256];
  red[t]=v*v; __syncthreads();
  for (int off=128;off>0;off>>=1){ if (t<off) red[t]+=red[t+off]; __syncthreads(); }
  float nrm = fmaxf(sqrtf(red[0]), 1e-12f);
  g_nf[(size_t)i*PROJD+t] = v/nrm;
}

// 12. SupCon per-row
__global__ void supcon_kernel() {
  int i=blockIdx.x, t=threadIdx.x;
  __shared__ float nfi[256];
  __shared__ float rp[256], ra[256]; __shared__ int rc[256];
  nfi[t] = g_nf[(size_t)i*PROJD+t];
  __syncthreads();
  int li=g_labels[i], vi=g_valid[i];
  float psum=0.f, asum=0.f; int pcnt=0;
  for (int j=t;j<NROI;j+=256) {
    const float* nj = g_nf + (size_t)j*PROJD;
    float dot=0.f;
#pragma unroll 8
    for (int c=0;c<256;c++) dot += nfi[c]*nj[c];
    float es = expf(dot*(1.f/0.07f));
    int vj=g_valid[j];
    int nd = (j!=i), vv = vi && vj;
    int isp = (g_labels[j]==li) && nd && vv;
    int ism = nd && vv;
    if (isp) { psum+=es; pcnt++; }
    if (ism) asum+=es;
  }
  rp[t]=psum; ra[t]=asum; rc[t]=pcnt; __syncthreads();
  for (int off=128;off>0;off>>=1) {
    if (t<off){ rp[t]+=rp[t+off]; ra[t]+=ra[t+off]; rc[t]+=rc[t+off]; }
    __syncthreads();
  }
  if (t==0) {
    float ratio = rp[0]/(ra[0]+1e-12f);
    float l = -logf(ratio+1e-12f);
    int active = vi && (rc[0]>0);
    g_rowl[i] = active ? l : 0.f;
    g_rowact[i] = active;
  }
}

// 13. finalize
__global__ void finalize_kernel(float* out) {
  int t=threadIdx.x;
  __shared__ float rl[256]; __shared__ int rc[256];
  float s=0.f; int c=0;
  for (int i=t;i<NROI;i+=256){ s+=g_rowl[i]; c+=g_rowact[i]; }
  rl[t]=s; rc[t]=c; __syncthreads();
  for (int off=128;off>0;off>>=1){ if (t<off){ rl[t]+=rl[t+off]; rc[t]+=rc[t+off]; } __syncthreads(); }
  if (t==0) out[0] = (rc[0]>0) ? rl[0]/(float)max(rc[0],1) : 0.f;
}

extern "C" void kernel_launch(void* const* d_in, const int* in_sizes, int n_in,
                              void* d_out, int out_size) {
  const float* clip   = (const float*)d_in[0];
  const float* gt     = (const float*)d_in[1];
  const float* conv_w = (const float*)d_in[2];
  const float* conv_b = (const float*)d_in[3];
  const float* cls_w  = (const float*)d_in[4];
  const float* cls_b  = (const float*)d_in[5];
  const float* reg_w  = (const float*)d_in[6];
  const float* reg_b  = (const float*)d_in[7];
  const float* pw1    = (const float*)d_in[8];
  const float* pb1    = (const float*)d_in[9];
  const float* pw2    = (const float*)d_in[10];
  const float* pb2    = (const float*)d_in[11];

  cudaFuncSetAttribute(conv_mma_kernel, cudaFuncAttributeMaxDynamicSharedMemorySize, CONV_SMEM);

  build_split_spatial<<<MROWS, 256>>>(clip);
  split_w_kernel<<<(OC*CDIM)/256, 256>>>(conv_w);
  conv_mma_kernel<<<dim3(4,64), 256, CONV_SMEM>>>(conv_b);
  heads_kernel<<<MROWS/8, 256>>>(cls_w, cls_b, reg_w, reg_b);
  topk_kernel<<<NB, 256>>>();
  nms_kernel<<<NB, 32>>>();
  integral_rows_kernel<<<NB, 256>>>(gt);
  integral_cols_kernel<<<NB, 256>>>();
  labels_kernel<<<(NROI+255)/256, 256>>>();
  roi_align_kernel<<<NROI, 256>>>();
  gemm_abt_kernel<<<dim3(4,15), 256>>>(pw1, pb1, 0, CDIM, 1);
  gemm_abt_kernel<<<dim3(4,15), 256>>>(pw2, pb2, 1, PROJD, 0);
  normalize_kernel<<<NROI, 256>>>();
  supcon_kernel<<<NROI, 256>>>();
  finalize_kernel<<<1, 256>>>((float*)d_out);
}

// round 11
// speedup vs baseline: 1.5465x; 1.2811x over previous
#include <cuda_runtime.h>
#include <cuda_fp16.h>
#include <math.h>
#include <stdint.h>

#define NB 32
#define CDIM 1024
#define FE 16
#define NANC 9
#define KTOP 30
#define NROI (NB*KTOP)
#define PROJD 256
#define OC 512
#define NPOS (FE*FE)
#define MROWS (NB*NPOS)

__device__ float g_S[MROWS*CDIM];
__device__ float g_X[MROWS*OC];
__device__ float g_scores[NB*NPOS*NANC];
__device__ float g_boxes[NB*NPOS*NANC*4];
__device__ float g_rois[NROI*4];
__device__ int   g_valid[NROI];
__device__ float g_I[NB*257*257];
__device__ float g_pooled[NROI*CDIM];
__device__ float g_h[NROI*PROJD];
__device__ float g_proj[NROI*PROJD];
__device__ float g_nf[NROI*PROJD];
__device__ int   g_labels[NROI];
__device__ float g_rowl[NROI];
__device__ int   g_rowact[NROI];

// fp16 2-way splits (residual pre-scaled by 2048): A spatial [m][c], B weights [tap][o][c]
__device__ __align__(16) __half gA0[MROWS*CDIM];
__device__ __align__(16) __half gA1[MROWS*CDIM];
__device__ __align__(16) __half gB0[9*OC*CDIM];
__device__ __align__(16) __half gB1[9*OC*CDIM];

__device__ __forceinline__ uint32_t smem_u32(const void* p) {
  uint32_t a;
  asm("{ .reg .u64 t; cvta.to.shared.u64 t, %1; cvt.u32.u64 %0, t; }" : "=r"(a) : "l"(p));
  return a;
}

// 1. spatial: clip[1+p][b][c] -> g_S (fp32) + fp16 split
__global__ void build_split_spatial(const float* __restrict__ clip) {
  int bx = blockIdx.x; int b = bx >> 8, p = bx & 255;
  const float* src = clip + (size_t)(1+p)*NB*CDIM + (size_t)b*CDIM;
#pragma unroll
  for (int q = 0; q < 4; q++) {
    int c = threadIdx.x + q*256;
    float v = src[c];
    size_t di = (size_t)bx*CDIM + c;
    g_S[di] = v;
    __half h = __float2half(v);
    float r1 = (v - __half2float(h)) * 2048.f;
    gA0[di] = h; gA1[di] = __float2half(r1);
  }
}

// 2. weights conv_w[o][c][t] -> gB{0,1}[t][o][c]
__global__ void split_w_kernel(const float* __restrict__ conv_w) {
  int e = blockIdx.x*256 + threadIdx.x; // o*1024+c
  int o = e >> 10, c = e & 1023;
  const float* src = conv_w + (size_t)e*9;
#pragma unroll
  for (int t = 0; t < 9; t++) {
    float v = src[t];
    __half h = __float2half(v);
    float r1 = (v - __half2float(h)) * 2048.f;
    size_t di = ((size_t)t*OC + o)*CDIM + c;
    gB0[di] = h; gB1[di] = __float2half(r1);
  }
}

// 3. conv 3x3 via mma.sync fp16 (HMMA), 2-way split, 3 chains, fp32 acc.
//    CTA 128x128, 8 warps (2x4), warp tile 64x32, k-step 16, 576 stages.
#define ASTRIDE 48
#define SPL_SZ (128*ASTRIDE)
#define STAGE_SZ (4*SPL_SZ)
#define CONV_SMEM (2*STAGE_SZ)

#define CPA16(dst, src, sz) \
  asm volatile("cp.async.cg.shared.global [%0], [%1], 16, %2;" :: "r"(dst), "l"(src), "r"(sz))
#define LDSM4(r0,r1,r2,r3,addr) \
  asm volatile("ldmatrix.sync.aligned.m8n8.x4.shared.b16 {%0,%1,%2,%3}, [%4];" \
    : "=r"(r0),"=r"(r1),"=r"(r2),"=r"(r3) : "r"(addr))
#define MMA16816(d0,d1,d2,d3,a0,a1,a2,a3,b0,b1) \
  asm volatile("mma.sync.aligned.m16n8k16.row.col.f32.f16.f16.f32 " \
    "{%0,%1,%2,%3}, {%4,%5,%6,%7}, {%8,%9}, {%0,%1,%2,%3};" \
    : "+f"(d0),"+f"(d1),"+f"(d2),"+f"(d3) \
    : "r"(a0),"r"(a1),"r"(a2),"r"(a3),"r"(b0),"r"(b1))

__global__ void __launch_bounds__(256, 1) conv_mma_kernel(const float* __restrict__ convb) {
  extern __shared__ __align__(128) char smem[];
  uint32_t sb = smem_u32(smem);
  const int tid = threadIdx.x, wid = tid >> 5, lane = tid & 31;
  const int bn = blockIdx.x*128, bm = blockIdx.y*128;
  const int wm = (wid >> 2)*64, wn = (wid & 3)*32;

  const int lrow = tid >> 1, lchunk = tid & 1;
  const int am = bm + lrow;
  const int ab = am >> 8, apos = am & 255, api = apos >> 4, apj = apos & 15;

  // accP = a0b0 chain, accQ = (a0b1 + a1b0) chain (scaled by 2048)
  float accP[4][4][4], accQ[4][4][4];
#pragma unroll
  for (int i = 0; i < 4; i++)
#pragma unroll
    for (int j = 0; j < 4; j++)
#pragma unroll
      for (int k = 0; k < 4; k++) { accP[i][j][k] = 0.f; accQ[i][j][k] = 0.f; }

  const __half* gAp[2] = {gA0, gA1};
  const __half* gBp[2] = {gB0, gB1};

  auto issue = [&](int s) {
    uint32_t dst = sb + (uint32_t)(s & 1)*STAGE_SZ;
    int tap = s >> 6, kc = s & 63;
    int di = tap/3 - 1, dj = tap - (tap/3)*3 - 1;
    int ii = api + di, jj = apj + dj;
    bool ok = ((unsigned)ii < 16u) && ((unsigned)jj < 16u);
    size_t asrc = ok ? ((size_t)((ab<<8)+(ii<<4)+jj))*CDIM + kc*16 + lchunk*8 : 0;
    int asz = ok ? 16 : 0;
    uint32_t adst = dst + lrow*ASTRIDE + lchunk*16;
    CPA16(adst + 0*SPL_SZ, gAp[0] + asrc, asz);
    CPA16(adst + 1*SPL_SZ, gAp[1] + asrc, asz);
    size_t bsrc = ((size_t)tap*OC + bn + lrow)*CDIM + kc*16 + lchunk*8;
    uint32_t bdst = dst + 2*SPL_SZ + lrow*ASTRIDE + lchunk*16;
    CPA16(bdst + 0*SPL_SZ, gBp[0] + bsrc, 16);
    CPA16(bdst + 1*SPL_SZ, gBp[1] + bsrc, 16);
    asm volatile("cp.async.commit_group;" ::: "memory");
  };

  issue(0);
  issue(1);

  const uint32_t a_off = (uint32_t)(wm + (lane & 15))*ASTRIDE + (uint32_t)(lane >> 4)*16;
  const uint32_t b_off = (uint32_t)(wn + (lane & 7) + ((lane >> 4) << 3))*ASTRIDE
                       + (uint32_t)((lane >> 3) & 1)*16;

  for (int s = 0; s < 576; s++) {
    asm volatile("cp.async.wait_group 1;" ::: "memory");
    __syncthreads();
    uint32_t base = sb + (uint32_t)(s & 1)*STAGE_SZ;

    uint32_t Ar[2][4][4];
    uint32_t Br[2][4][2];
#pragma unroll
    for (int p = 0; p < 2; p++) {
#pragma unroll
      for (int i = 0; i < 4; i++) {
        uint32_t ad = base + p*SPL_SZ + a_off + (uint32_t)(i*16)*ASTRIDE;
        LDSM4(Ar[p][i][0], Ar[p][i][1], Ar[p][i][2], Ar[p][i][3], ad);
      }
#pragma unroll
      for (int j = 0; j < 2; j++) {
        uint32_t bd = base + (2+p)*SPL_SZ + b_off + (uint32_t)(j*16)*ASTRIDE;
        LDSM4(Br[p][2*j][0], Br[p][2*j][1], Br[p][2*j+1][0], Br[p][2*j+1][1], bd);
      }
    }
    __syncthreads();
    if (s + 2 < 576) issue(s + 2);
    else asm volatile("cp.async.commit_group;" ::: "memory");

#pragma unroll
    for (int i = 0; i < 4; i++)
#pragma unroll
      for (int jn = 0; jn < 4; jn++) {
        MMA16816(accP[i][jn][0], accP[i][jn][1], accP[i][jn][2], accP[i][jn][3],
                 Ar[0][i][0], Ar[0][i][1], Ar[0][i][2], Ar[0][i][3],
                 Br[0][jn][0], Br[0][jn][1]);
        MMA16816(accQ[i][jn][0], accQ[i][jn][1], accQ[i][jn][2], accQ[i][jn][3],
                 Ar[0][i][0], Ar[0][i][1], Ar[0][i][2], Ar[0][i][3],
                 Br[1][jn][0], Br[1][jn][1]);
        MMA16816(accQ[i][jn][0], accQ[i][jn][1], accQ[i][jn][2], accQ[i][jn][3],
                 Ar[1][i][0], Ar[1][i][1], Ar[1][i][2], Ar[1][i][3],
                 Br[0][jn][0], Br[0][jn][1]);
      }
  }

  const int gi = lane >> 2, t4 = lane & 3;
  const float RS = 1.f/2048.f;
#pragma unroll
  for (int i = 0; i < 4; i++) {
#pragma unroll
    for (int jn = 0; jn < 4; jn++) {
      int r0 = bm + wm + i*16 + gi;
      int c0 = bn + wn + jn*8 + t4*2;
      float b0v = convb[c0], b1v = convb[c0+1];
      float v0 = accP[i][jn][0] + accQ[i][jn][0]*RS;
      float v1 = accP[i][jn][1] + accQ[i][jn][1]*RS;
      float v2 = accP[i][jn][2] + accQ[i][jn][2]*RS;
      float v3 = accP[i][jn][3] + accQ[i][jn][3]*RS;
      g_X[(size_t)r0*OC + c0]         = fmaxf(v0 + b0v, 0.f);
      g_X[(size_t)r0*OC + c0 + 1]     = fmaxf(v1 + b1v, 0.f);
      g_X[(size_t)(r0+8)*OC + c0]     = fmaxf(v2 + b0v, 0.f);
      g_X[(size_t)(r0+8)*OC + c0 + 1] = fmaxf(v3 + b1v, 0.f);
    }
  }
}

// 4. heads + anchor decode + sigmoid. One warp per position.
__global__ void heads_kernel(const float* __restrict__ cls_w, const float* __restrict__ cls_b,
                             const float* __restrict__ reg_w, const float* __restrict__ reg_b) {
  int w = threadIdx.x>>5, lane = threadIdx.x&31;
  int m = blockIdx.x*8 + w;
  float ac[9], ar[36];
#pragma unroll
  for (int a=0;a<9;a++) ac[a]=0.f;
#pragma unroll
  for (int a=0;a<36;a++) ar[a]=0.f;
  const float* xr = g_X + (size_t)m*OC;
  for (int c=lane;c<OC;c+=32) {
    float xv = xr[c];
#pragma unroll
    for (int a=0;a<9;a++) ac[a] += xv*cls_w[a*OC+c];
#pragma unroll
    for (int a=0;a<36;a++) ar[a] += xv*reg_w[a*OC+c];
  }
  __shared__ float hs[8][46];
#pragma unroll
  for (int a=0;a<9;a++){ float v=ac[a];
    for (int o=16;o>0;o>>=1) v += __shfl_xor_sync(0xffffffffu,v,o);
    if (lane==0) hs[w][a]=v; }
#pragma unroll
  for (int a=0;a<36;a++){ float v=ar[a];
    for (int o=16;o>0;o>>=1) v += __shfl_xor_sync(0xffffffffu,v,o);
    if (lane==0) hs[w][9+a]=v; }
  __syncwarp();
  if (lane<9) {
    int a=lane, b=m>>8, pos=m&255, i=pos>>4, j=pos&15;
    float cls = hs[w][a] + cls_b[a];
    float r0 = hs[w][9+a*4+0]+reg_b[a*4+0], r1 = hs[w][9+a*4+1]+reg_b[a*4+1];
    float r2 = hs[w][9+a*4+2]+reg_b[a*4+2], r3 = hs[w][9+a*4+3]+reg_b[a*4+3];
    const double scl[3]={8.0,16.0,32.0}, rat[3]={0.5,1.0,2.0};
    double s=scl[a/3], rr=rat[a-(a/3)*3];
    double wD=s*sqrt(rr), hD=s/sqrt(rr);
    double xcD=(j+0.5)*16.0, ycD=(i+0.5)*16.0;
    float ax1=(float)(xcD-wD*0.5), ay1=(float)(ycD-hD*0.5);
    float ax2=(float)(xcD+wD*0.5), ay2=(float)(ycD+hD*0.5);
    float aw=ax2-ax1, ah=ay2-ay1, ctx=ax1+0.5f*aw, cty=ay1+0.5f*ah;
    float cx=r0*aw+ctx, cy=r1*ah+cty;
    float pw=expf(r2)*aw, ph=expf(r3)*ah;
    float x1=fminf(fmaxf(cx-0.5f*pw,0.f),256.f), y1=fminf(fmaxf(cy-0.5f*ph,0.f),256.f);
    float x2=fminf(fmaxf(cx+0.5f*pw,0.f),256.f), y2=fminf(fmaxf(cy+0.5f*ph,0.f),256.f);
    if (x2-x1<1.f) x2=x1+1.f;
    if (y2-y1<1.f) y2=y1+1.f;
    int aidx = pos*9+a;
    g_scores[b*2304+aidx] = 1.f/(1.f+expf(-cls));
    float* bp = &g_boxes[((size_t)b*2304+aidx)*4];
    bp[0]=x1; bp[1]=y1; bp[2]=x2; bp[3]=y2;
  }
}

// 5. stable top-30 per image
__global__ void topk_kernel() {
  int b = blockIdx.x, tid = threadIdx.x;
  __shared__ unsigned sel[72];
  __shared__ float sv[256]; __shared__ int si[256];
  if (tid<72) sel[tid]=0u;
  __syncthreads();
  const float* sc = g_scores + (size_t)b*2304;
  for (int k=0;k<KTOP;k++) {
    float bv=-1e30f; int bi=1<<30;
    for (int e=tid;e<2304;e+=256) {
      if (sel[e>>5] & (1u<<(e&31))) continue;
      float v=sc[e];
      if (v>bv || (v==bv && e<bi)) { bv=v; bi=e; }
    }
    sv[tid]=bv; si[tid]=bi; __syncthreads();
    for (int off=128;off>0;off>>=1) {
      if (tid<off) {
        float v2=sv[tid+off]; int i2=si[tid+off];
        if (v2>sv[tid] || (v2==sv[tid] && i2<si[tid])) { sv[tid]=v2; si[tid]=i2; }
      }
      __syncthreads();
    }
    if (tid==0) {
      int best=si[0];
      sel[best>>5] |= (1u<<(best&31));
      const float* bp=&g_boxes[((size_t)b*2304+best)*4];
      float* rp=&g_rois[(b*KTOP+k)*4];
      rp[0]=bp[0]; rp[1]=bp[1]; rp[2]=bp[2]; rp[3]=bp[3];
    }
    __syncthreads();
  }
}

// 6. greedy NMS
__global__ void nms_kernel() {
  int b=blockIdx.x, t=threadIdx.x;
  __shared__ float x1s[30],y1s[30],x2s[30],y2s[30],ars[30];
  __shared__ int keep[30];
  if (t<30) {
    const float* rp=&g_rois[(b*KTOP+t)*4];
    x1s[t]=rp[0]; y1s[t]=rp[1]; x2s[t]=rp[2]; y2s[t]=rp[3];
    ars[t]=(rp[2]-rp[0])*(rp[3]-rp[1]); keep[t]=1;
  }
  __syncwarp();
  for (int i=0;i<KTOP;i++) {
    if (t<30 && t>i && keep[i]) {
      float iw=fmaxf(fminf(x2s[i],x2s[t])-fmaxf(x1s[i],x1s[t]),0.f);
      float ih=fmaxf(fminf(y2s[i],y2s[t])-fmaxf(y1s[i],y1s[t]),0.f);
      float inter=iw*ih;
      if (inter/(ars[i]+ars[t]-inter) > 0.85f) keep[t]=0;
    }
    __syncwarp();
  }
  if (t<30) g_valid[b*KTOP+t]=keep[t];
}

// 7. integral images
__global__ void integral_rows_kernel(const float* __restrict__ gt) {
  int b=blockIdx.x, t=threadIdx.x;
  float* I = g_I + (size_t)b*66049;
  I[t]=0.f; if (t==0) I[256]=0.f;
  const float* g = gt + (size_t)b*65536 + (size_t)t*256;
  float* row = I + (size_t)(t+1)*257;
  row[0]=0.f; float run=0.f;
  for (int x=0;x<256;x++){ run+=g[x]; row[x+1]=run; }
}
__global__ void integral_cols_kernel() {
  int b=blockIdx.x, x=threadIdx.x+1;
  float* I = g_I + (size_t)b*66049;
  float run=0.f;
  for (int y=1;y<=256;y++){ run += I[(size_t)y*257+x]; I[(size_t)y*257+x]=run; }
}

// 8. ROI labels
__global__ void labels_kernel() {
  int r = blockIdx.x*blockDim.x + threadIdx.x;
  if (r>=NROI) return;
  int b = r/KTOP;
  const float* roi=&g_rois[r*4];
  int x1=min(max((int)roi[0],0),256), y1=min(max((int)roi[1],0),256);
  int x2=min(max((int)roi[2],0),256), y2=min(max((int)roi[3],0),256);
  const float* I = g_I + (size_t)b*66049;
  float s = I[(size_t)y2*257+x2]-I[(size_t)y1*257+x2]-I[(size_t)y2*257+x1]+I[(size_t)y1*257+x1];
  int cnt=(y2-y1)*(x2-x1);
  g_labels[r] = (cnt>0) ? ((s/(float)max(cnt,1))>0.5f ? 1 : 0) : 0;
}

// 9. ROI align
__global__ void roi_align_kernel() {
  int r=blockIdx.x, t=threadIdx.x, b=r/KTOP;
  __shared__ float w00[49],w01[49],w10[49],w11[49];
  __shared__ int o00[49],o01[49],o10[49],o11[49],pok[49];
  if (t<49) {
    const float* roi=&g_rois[r*4];
    const float sc=1.f/16.f;
    float x1=roi[0]*sc, y1=roi[1]*sc;
    float rw=fmaxf(roi[2]*sc-x1,1.f), rh=fmaxf(roi[3]*sc-y1,1.f);
    int p=t/7, q=t-p*7;
    float X=x1+(q+0.5f)*(rw/7.f), Y=y1+(p+0.5f)*(rh/7.f);
    int ok = (Y>-1.f)&&(Y<16.f)&&(X>-1.f)&&(X<16.f);
    float Xc=fminf(fmaxf(X,0.f),15.f), Yc=fminf(fmaxf(Y,0.f),15.f);
    int x0=(int)floorf(Xc), y0=(int)floorf(Yc);
    int x1i=min(x0+1,15), y1i=min(y0+1,15);
    float lx=Xc-(float)x0, ly=Yc-(float)y0, hx=1.f-lx, hy=1.f-ly;
    w00[t]=hy*hx; w01[t]=hy*lx; w10[t]=ly*hx; w11[t]=ly*lx;
    o00[t]=(y0*16+x0)*CDIM; o01[t]=(y0*16+x1i)*CDIM;
    o10[t]=(y1i*16+x0)*CDIM; o11[t]=(y1i*16+x1i)*CDIM;
    pok[t]=ok;
  }
  __syncthreads();
  const float* Sb = g_S + (size_t)b*NPOS*CDIM;
  float a0=0,a1=0,a2=0,a3=0;
  for (int pt=0;pt<49;pt++) {
    if (!pok[pt]) continue;
    const float *p00=Sb+o00[pt],*p01=Sb+o01[pt],*p10=Sb+o10[pt],*p11=Sb+o11[pt];
    float W00=w00[pt],W01=w01[pt],W10=w10[pt],W11=w11[pt];
    a0 += W00*p00[t]     + W01*p01[t]     + W10*p10[t]     + W11*p11[t];
    a1 += W00*p00[t+256] + W01*p01[t+256] + W10*p10[t+256] + W11*p11[t+256];
    a2 += W00*p00[t+512] + W01*p01[t+512] + W10*p10[t+512] + W11*p11[t+512];
    a3 += W00*p00[t+768] + W01*p01[t+768] + W10*p10[t+768] + W11*p11[t+768];
  }
  float* out = g_pooled + (size_t)r*CDIM;
  out[t]=a0/49.f; out[t+256]=a1/49.f; out[t+512]=a2/49.f; out[t+768]=a3/49.f;
}

// 10. C = A*B^T + bias
__global__ __launch_bounds__(256) void gemm_abt_kernel(const float* __restrict__ Bm,
                                                       const float* __restrict__ bias,
                                                       int mode, int K, int relu) {
  const float* A = (mode==0) ? g_pooled : g_h;
  float* C = (mode==0) ? g_h : g_proj;
  const int N=256;
  const int bm = blockIdx.y*64, bn = blockIdx.x*64, tid = threadIdx.x;
  __shared__ float As[16][68];
  __shared__ float Bs[16][68];
  const int lr = tid>>2, lk = (tid&3)<<2;
  const int tm = (tid>>4)<<2, tn = (tid&15)<<2;
  float acc[4][4];
#pragma unroll
  for (int r=0;r<4;r++)
#pragma unroll
    for (int c=0;c<4;c++) acc[r][c]=0.f;
  for (int k0=0;k0<K;k0+=16) {
    float4 a4 = *(const float4*)&A[(size_t)(bm+lr)*K + k0+lk];
    float4 b4 = *(const float4*)&Bm[(size_t)(bn+lr)*K + k0+lk];
    __syncthreads();
    As[lk+0][lr]=a4.x; As[lk+1][lr]=a4.y; As[lk+2][lr]=a4.z; As[lk+3][lr]=a4.w;
    Bs[lk+0][lr]=b4.x; Bs[lk+1][lr]=b4.y; Bs[lk+2][lr]=b4.z; Bs[lk+3][lr]=b4.w;
    __syncthreads();
#pragma unroll
    for (int kk=0;kk<16;kk++) {
      float4 av=*(const float4*)&As[kk][tm];
      float4 bv=*(const float4*)&Bs[kk][tn];
      float aa[4]={av.x,av.y,av.z,av.w}, bb[4]={bv.x,bv.y,bv.z,bv.w};
#pragma unroll
      for (int r=0;r<4;r++)
#pragma unroll
        for (int c=0;c<4;c++) acc[r][c]+=aa[r]*bb[c];
    }
  }
#pragma unroll
  for (int r=0;r<4;r++) {
    size_t off=(size_t)(bm+tm+r)*N + bn+tn;
#pragma unroll
    for (int c=0;c<4;c++) {
      float v=acc[r][c]+bias[bn+tn+c];
      if (relu) v=fmaxf(v,0.f);
      C[off+c]=v;
    }
  }
}

// 11. row L2 normalize
__global__ void normalize_kernel() {
  int i=blockIdx.x, t=threadIdx.x;
  float v = g_proj[(size_t)i*PROJD+t];
  __shared__ float red[256];
  red[t]=v*v; __syncthreads();
  for (int off=128;off>0;off>>=1){ if (t<off) red[t]+=red[t+off]; __syncthreads(); }
  float nrm = fmaxf(sqrtf(red[0]), 1e-12f);
  g_nf[(size_t)i*PROJD+t] = v/nrm;
}

// 12. SupCon per-row
__global__ void supcon_kernel() {
  int i=blockIdx.x, t=threadIdx.x;
  __shared__ float nfi[256];
  __shared__ float rp[256], ra[256]; __shared__ int rc[256];
  nfi[t] = g_nf[(size_t)i*PROJD+t];
  __syncthreads();
  int li=g_labels[i], vi=g_valid[i];
  float psum=0.f, asum=0.f; int pcnt=0;
  for (int j=t;j<NROI;j+=256) {
    const float* nj = g_nf + (size_t)j*PROJD;
    float dot=0.f;
#pragma unroll 8
    for (int c=0;c<256;c++) dot += nfi[c]*nj[c];
    float es = expf(dot*(1.f/0.07f));
    int vj=g_valid[j];
    int nd = (j!=i), vv = vi && vj;
    int isp = (g_labels[j]==li) && nd && vv;
    int ism = nd && vv;
    if (isp) { psum+=es; pcnt++; }
    if (ism) asum+=es;
  }
  rp[t]=psum; ra[t]=asum; rc[t]=pcnt; __syncthreads();
  for (int off=128;off>0;off>>=1) {
    if (t<off){ rp[t]+=rp[t+off]; ra[t]+=ra[t+off]; rc[t]+=rc[t+off]; }
    __syncthreads();
  }
  if (t==0) {
    float ratio = rp[0]/(ra[0]+1e-12f);
    float l = -logf(ratio+1e-12f);
    int active = vi && (rc[0]>0);
    g_rowl[i] = active ? l : 0.f;
    g_rowact[i] = active;
  }
}

// 13. finalize
__global__ void finalize_kernel(float* out) {
  int t=threadIdx.x;
  __shared__ float rl[256]; __shared__ int rc[256];
  float s=0.f; int c=0;
  for (int i=t;i<NROI;i+=256){ s+=g_rowl[i]; c+=g_rowact[i]; }
  rl[t]=s; rc[t]=c; __syncthreads();
  for (int off=128;off>0;off>>=1){ if (t<off){ rl[t]+=rl[t+off]; rc[t]+=rc[t+off]; } __syncthreads(); }
  if (t==0) out[0] = (rc[0]>0) ? rl[0]/(float)max(rc[0],1) : 0.f;
}

extern "C" void kernel_launch(void* const* d_in, const int* in_sizes, int n_in,
                              void* d_out, int out_size) {
  const float* clip   = (const float*)d_in[0];
  const float* gt     = (const float*)d_in[1];
  const float* conv_w = (const float*)d_in[2];
  const float* conv_b = (const float*)d_in[3];
  const float* cls_w  = (const float*)d_in[4];
  const float* cls_b  = (const float*)d_in[5];
  const float* reg_w  = (const float*)d_in[6];
  const float* reg_b  = (const float*)d_in[7];
  const float* pw1    = (const float*)d_in[8];
  const float* pb1    = (const float*)d_in[9];
  const float* pw2    = (const float*)d_in[10];
  const float* pb2    = (const float*)d_in[11];

  cudaFuncSetAttribute(conv_mma_kernel, cudaFuncAttributeMaxDynamicSharedMemorySize, CONV_SMEM);

  build_split_spatial<<<MROWS, 256>>>(clip);
  split_w_kernel<<<(OC*CDIM)/256, 256>>>(conv_w);
  conv_mma_kernel<<<dim3(4,64), 256, CONV_SMEM>>>(conv_b);
  heads_kernel<<<MROWS/8, 256>>>(cls_w, cls_b, reg_w, reg_b);
  topk_kernel<<<NB, 256>>>();
  nms_kernel<<<NB, 32>>>();
  integral_rows_kernel<<<NB, 256>>>(gt);
  integral_cols_kernel<<<NB, 256>>>();
  labels_kernel<<<(NROI+255)/256, 256>>>();
  roi_align_kernel<<<NROI, 256>>>();
  gemm_abt_kernel<<<dim3(4,15), 256>>>(pw1, pb1, 0, CDIM, 1);
  gemm_abt_kernel<<<dim3(4,15), 256>>>(pw2, pb2, 1, PROJD, 0);
  normalize_kernel<<<NROI, 256>>>();
  supcon_kernel<<<NROI, 256>>>();
  finalize_kernel<<<1, 256>>>((float*)d_out);
}

// round 16
// speedup vs baseline: 2.7870x; 1.8022x over previous
#include <cuda_runtime.h>
#include <cuda_fp16.h>
#include <math.h>
#include <stdint.h>

#define NB 32
#define CDIM 1024
#define FE 16
#define NANC 9
#define KTOP 30
#define NROI (NB*KTOP)
#define PROJD 256
#define OC 512
#define NPOS (FE*FE)
#define MROWS (NB*NPOS)

__device__ float g_S[MROWS*CDIM];
__device__ float g_X[MROWS*OC];
__device__ float g_scores[NB*NPOS*NANC];
__device__ float g_boxes[NB*NPOS*NANC*4];
__device__ float g_rois[NROI*4];
__device__ int   g_valid[NROI];
__device__ float g_I[NB*257*257];
__device__ float g_pooled[NROI*CDIM];
__device__ float g_h[NROI*PROJD];
__device__ float g_proj[NROI*PROJD];
__device__ float g_nf[NROI*PROJD];
__device__ float g_sim[NROI*NROI];
__device__ int   g_labels[NROI];
__device__ float g_rowl[NROI];
__device__ int   g_rowact[NROI];

// fp16 2-way splits (residual pre-scaled by 2048)
__device__ __align__(16) __half gA0[MROWS*CDIM];
__device__ __align__(16) __half gA1[MROWS*CDIM];
__device__ __align__(16) __half gB0[9*OC*CDIM];
__device__ __align__(16) __half gB1[9*OC*CDIM];

__device__ __forceinline__ uint32_t smem_u32(const void* p) {
  uint32_t a;
  asm("{ .reg .u64 t; cvta.to.shared.u64 t, %1; cvt.u32.u64 %0, t; }" : "=r"(a) : "l"(p));
  return a;
}

// 1. spatial: clip[1+p][b][c] -> g_S (fp32) + fp16 split
__global__ void build_split_spatial(const float* __restrict__ clip) {
  int bx = blockIdx.x; int b = bx >> 8, p = bx & 255;
  const float* src = clip + (size_t)(1+p)*NB*CDIM + (size_t)b*CDIM;
#pragma unroll
  for (int q = 0; q < 4; q++) {
    int c = threadIdx.x + q*256;
    float v = src[c];
    size_t di = (size_t)bx*CDIM + c;
    g_S[di] = v;
    __half h = __float2half(v);
    float r1 = (v - __half2float(h)) * 2048.f;
    gA0[di] = h; gA1[di] = __float2half(r1);
  }
}

// 2. weights conv_w[o][c][t] -> gB{0,1}[t][o][c]
__global__ void split_w_kernel(const float* __restrict__ conv_w) {
  int e = blockIdx.x*256 + threadIdx.x; // o*1024+c
  int o = e >> 10, c = e & 1023;
  const float* src = conv_w + (size_t)e*9;
#pragma unroll
  for (int t = 0; t < 9; t++) {
    float v = src[t];
    __half h = __float2half(v);
    float r1 = (v - __half2float(h)) * 2048.f;
    size_t di = ((size_t)t*OC + o)*CDIM + c;
    gB0[di] = h; gB1[di] = __float2half(r1);
  }
}

// 3. conv 3x3 via mma.sync fp16, 2-way split, 3 chains, fp32 acc.
//    CTA 128x128, 8 warps, warp tile 64x32, k-step 16, 576 stages, ring-4.
#define ASTRIDE 48
#define SPL_SZ (128*ASTRIDE)
#define STAGE_SZ (4*SPL_SZ)
#define CONV_SMEM (4*STAGE_SZ)

#define CPA16(dst, src, sz) \
  asm volatile("cp.async.cg.shared.global [%0], [%1], 16, %2;" :: "r"(dst), "l"(src), "r"(sz))
#define LDSM4(r0,r1,r2,r3,addr) \
  asm volatile("ldmatrix.sync.aligned.m8n8.x4.shared.b16 {%0,%1,%2,%3}, [%4];" \
    : "=r"(r0),"=r"(r1),"=r"(r2),"=r"(r3) : "r"(addr))
#define MMA16816(d0,d1,d2,d3,a0,a1,a2,a3,b0,b1) \
  asm volatile("mma.sync.aligned.m16n8k16.row.col.f32.f16.f16.f32 " \
    "{%0,%1,%2,%3}, {%4,%5,%6,%7}, {%8,%9}, {%0,%1,%2,%3};" \
    : "+f"(d0),"+f"(d1),"+f"(d2),"+f"(d3) \
    : "r"(a0),"r"(a1),"r"(a2),"r"(a3),"r"(b0),"r"(b1))

__global__ void __launch_bounds__(256, 1) conv_mma_kernel(const float* __restrict__ convb) {
  extern __shared__ __align__(128) char smem[];
  uint32_t sb = smem_u32(smem);
  const int tid = threadIdx.x, wid = tid >> 5, lane = tid & 31;
  const int bn = blockIdx.x*128, bm = blockIdx.y*128;
  const int wm = (wid >> 2)*64, wn = (wid & 3)*32;

  const int lrow = tid >> 1, lchunk = tid & 1;
  const int am = bm + lrow;
  const int ab = am >> 8, apos = am & 255, api = apos >> 4, apj = apos & 15;

  float accP[4][4][4], accQ[4][4][4];
#pragma unroll
  for (int i = 0; i < 4; i++)
#pragma unroll
    for (int j = 0; j < 4; j++)
#pragma unroll
      for (int k = 0; k < 4; k++) { accP[i][j][k] = 0.f; accQ[i][j][k] = 0.f; }

  const __half* gAp[2] = {gA0, gA1};
  const __half* gBp[2] = {gB0, gB1};

  auto issue = [&](int s) {
    uint32_t dst = sb + (uint32_t)(s & 3)*STAGE_SZ;
    int tap = s >> 6, kc = s & 63;
    int di = tap/3 - 1, dj = tap - (tap/3)*3 - 1;
    int ii = api + di, jj = apj + dj;
    bool ok = ((unsigned)ii < 16u) && ((unsigned)jj < 16u);
    size_t asrc = ok ? ((size_t)((ab<<8)+(ii<<4)+jj))*CDIM + kc*16 + lchunk*8 : 0;
    int asz = ok ? 16 : 0;
    uint32_t adst = dst + lrow*ASTRIDE + lchunk*16;
    CPA16(adst + 0*SPL_SZ, gAp[0] + asrc, asz);
    CPA16(adst + 1*SPL_SZ, gAp[1] + asrc, asz);
    size_t bsrc = ((size_t)tap*OC + bn + lrow)*CDIM + kc*16 + lchunk*8;
    uint32_t bdst = dst + 2*SPL_SZ + lrow*ASTRIDE + lchunk*16;
    CPA16(bdst + 0*SPL_SZ, gBp[0] + bsrc, 16);
    CPA16(bdst + 1*SPL_SZ, gBp[1] + bsrc, 16);
    asm volatile("cp.async.commit_group;" ::: "memory");
  };

  issue(0); issue(1); issue(2);

  const uint32_t a_off = (uint32_t)(wm + (lane & 15))*ASTRIDE + (uint32_t)(lane >> 4)*16;
  const uint32_t b_off = (uint32_t)(wn + (lane & 7) + ((lane >> 4) << 3))*ASTRIDE
                       + (uint32_t)((lane >> 3) & 1)*16;

  for (int s = 0; s < 576; s++) {
    asm volatile("cp.async.wait_group 2;" ::: "memory");
    __syncthreads();
    uint32_t base = sb + (uint32_t)(s & 3)*STAGE_SZ;

    uint32_t Ar[2][4][4];
    uint32_t Br[2][4][2];
#pragma unroll
    for (int p = 0; p < 2; p++) {
#pragma unroll
      for (int i = 0; i < 4; i++) {
        uint32_t ad = base + p*SPL_SZ + a_off + (uint32_t)(i*16)*ASTRIDE;
        LDSM4(Ar[p][i][0], Ar[p][i][1], Ar[p][i][2], Ar[p][i][3], ad);
      }
#pragma unroll
      for (int j = 0; j < 2; j++) {
        uint32_t bd = base + (2+p)*SPL_SZ + b_off + (uint32_t)(j*16)*ASTRIDE;
        LDSM4(Br[p][2*j][0], Br[p][2*j][1], Br[p][2*j+1][0], Br[p][2*j+1][1], bd);
      }
    }
    if (s + 3 < 576) issue(s + 3);
    else asm volatile("cp.async.commit_group;" ::: "memory");

#pragma unroll
    for (int i = 0; i < 4; i++)
#pragma unroll
      for (int jn = 0; jn < 4; jn++) {
        MMA16816(accP[i][jn][0], accP[i][jn][1], accP[i][jn][2], accP[i][jn][3],
                 Ar[0][i][0], Ar[0][i][1], Ar[0][i][2], Ar[0][i][3],
                 Br[0][jn][0], Br[0][jn][1]);
        MMA16816(accQ[i][jn][0], accQ[i][jn][1], accQ[i][jn][2], accQ[i][jn][3],
                 Ar[0][i][0], Ar[0][i][1], Ar[0][i][2], Ar[0][i][3],
                 Br[1][jn][0], Br[1][jn][1]);
        MMA16816(accQ[i][jn][0], accQ[i][jn][1], accQ[i][jn][2], accQ[i][jn][3],
                 Ar[1][i][0], Ar[1][i][1], Ar[1][i][2], Ar[1][i][3],
                 Br[0][jn][0], Br[0][jn][1]);
      }
  }

  const int gi = lane >> 2, t4 = lane & 3;
  const float RS = 1.f/2048.f;
#pragma unroll
  for (int i = 0; i < 4; i++) {
#pragma unroll
    for (int jn = 0; jn < 4; jn++) {
      int r0 = bm + wm + i*16 + gi;
      int c0 = bn + wn + jn*8 + t4*2;
      float b0v = convb[c0], b1v = convb[c0+1];
      float v0 = accP[i][jn][0] + accQ[i][jn][0]*RS;
      float v1 = accP[i][jn][1] + accQ[i][jn][1]*RS;
      float v2 = accP[i][jn][2] + accQ[i][jn][2]*RS;
      float v3 = accP[i][jn][3] + accQ[i][jn][3]*RS;
      g_X[(size_t)r0*OC + c0]         = fmaxf(v0 + b0v, 0.f);
      g_X[(size_t)r0*OC + c0 + 1]     = fmaxf(v1 + b1v, 0.f);
      g_X[(size_t)(r0+8)*OC + c0]     = fmaxf(v2 + b0v, 0.f);
      g_X[(size_t)(r0+8)*OC + c0 + 1] = fmaxf(v3 + b1v, 0.f);
    }
  }
}

// 4. heads: 8 warps = 4 positions x 2 halves (27/18 accumulators -> no spills)
__global__ void heads_kernel(const float* __restrict__ cls_w, const float* __restrict__ cls_b,
                             const float* __restrict__ reg_w, const float* __restrict__ reg_b) {
  int w = threadIdx.x>>5, lane = threadIdx.x&31;
  int posi = w>>1, half = w&1;
  int m = blockIdx.x*4 + posi;
  const float* xr = g_X + (size_t)m*OC;
  __shared__ float hs[4][46];
  if (half == 0) {
    float ac[9], ar[18];
#pragma unroll
    for (int a=0;a<9;a++) ac[a]=0.f;
#pragma unroll
    for (int a=0;a<18;a++) ar[a]=0.f;
    for (int c=lane;c<OC;c+=32) {
      float xv = xr[c];
#pragma unroll
      for (int a=0;a<9;a++) ac[a] += xv*cls_w[a*OC+c];
#pragma unroll
      for (int a=0;a<18;a++) ar[a] += xv*reg_w[a*OC+c];
    }
#pragma unroll
    for (int a=0;a<9;a++){ float v=ac[a];
      for (int o=16;o>0;o>>=1) v += __shfl_xor_sync(0xffffffffu,v,o);
      if (lane==0) hs[posi][a]=v; }
#pragma unroll
    for (int a=0;a<18;a++){ float v=ar[a];
      for (int o=16;o>0;o>>=1) v += __shfl_xor_sync(0xffffffffu,v,o);
      if (lane==0) hs[posi][9+a]=v; }
  } else {
    float ar[18];
#pragma unroll
    for (int a=0;a<18;a++) ar[a]=0.f;
    for (int c=lane;c<OC;c+=32) {
      float xv = xr[c];
#pragma unroll
      for (int a=0;a<18;a++) ar[a] += xv*reg_w[(18+a)*OC+c];
    }
#pragma unroll
    for (int a=0;a<18;a++){ float v=ar[a];
      for (int o=16;o>0;o>>=1) v += __shfl_xor_sync(0xffffffffu,v,o);
      if (lane==0) hs[posi][27+a]=v; }
  }
  __syncthreads();
  if (half==0 && lane<9) {
    int a=lane, b=m>>8, pos=m&255, i=pos>>4, j=pos&15;
    float cls = hs[posi][a] + cls_b[a];
    float r0 = hs[posi][9+a*4+0]+reg_b[a*4+0], r1 = hs[posi][9+a*4+1]+reg_b[a*4+1];
    float r2 = hs[posi][9+a*4+2]+reg_b[a*4+2], r3 = hs[posi][9+a*4+3]+reg_b[a*4+3];
    const double scl[3]={8.0,16.0,32.0}, rat[3]={0.5,1.0,2.0};
    double s=scl[a/3], rr=rat[a-(a/3)*3];
    double wD=s*sqrt(rr), hD=s/sqrt(rr);
    double xcD=(j+0.5)*16.0, ycD=(i+0.5)*16.0;
    float ax1=(float)(xcD-wD*0.5), ay1=(float)(ycD-hD*0.5);
    float ax2=(float)(xcD+wD*0.5), ay2=(float)(ycD+hD*0.5);
    float aw=ax2-ax1, ah=ay2-ay1, ctx=ax1+0.5f*aw, cty=ay1+0.5f*ah;
    float cx=r0*aw+ctx, cy=r1*ah+cty;
    float pw=expf(r2)*aw, ph=expf(r3)*ah;
    float x1=fminf(fmaxf(cx-0.5f*pw,0.f),256.f), y1=fminf(fmaxf(cy-0.5f*ph,0.f),256.f);
    float x2=fminf(fmaxf(cx+0.5f*pw,0.f),256.f), y2=fminf(fmaxf(cy+0.5f*ph,0.f),256.f);
    if (x2-x1<1.f) x2=x1+1.f;
    if (y2-y1<1.f) y2=y1+1.f;
    int aidx = pos*9+a;
    g_scores[b*2304+aidx] = 1.f/(1.f+expf(-cls));
    float* bp = &g_boxes[((size_t)b*2304+aidx)*4];
    bp[0]=x1; bp[1]=y1; bp[2]=x2; bp[3]=y2;
  }
}

// 5. stable top-30: smem scores, selected -> -inf, warp-shuffle argmax
__global__ void topk_kernel() {
  int b = blockIdx.x, tid = threadIdx.x, w = tid>>5, lane = tid&31;
  __shared__ float sc[2304];
  __shared__ float wv[8]; __shared__ int wi[8];
  const float* gs = g_scores + (size_t)b*2304;
  for (int e = tid; e < 2304; e += 256) sc[e] = gs[e];
  __syncthreads();
  for (int k=0;k<KTOP;k++) {
    float bv=-1e30f; int bi=1<<30;
    for (int e=tid;e<2304;e+=256) {
      float v=sc[e];
      if (v>bv || (v==bv && e<bi)) { bv=v; bi=e; }
    }
#pragma unroll
    for (int o=16;o>0;o>>=1) {
      float ov=__shfl_down_sync(0xffffffffu,bv,o);
      int   oi=__shfl_down_sync(0xffffffffu,bi,o);
      if (ov>bv || (ov==bv && oi<bi)) { bv=ov; bi=oi; }
    }
    if (lane==0) { wv[w]=bv; wi[w]=bi; }
    __syncthreads();
    if (tid==0) {
      float fv=wv[0]; int fi=wi[0];
#pragma unroll
      for (int q=1;q<8;q++) {
        if (wv[q]>fv || (wv[q]==fv && wi[q]<fi)) { fv=wv[q]; fi=wi[q]; }
      }
      const float* bp=&g_boxes[((size_t)b*2304+fi)*4];
      float* rp=&g_rois[(b*KTOP+k)*4];
      rp[0]=bp[0]; rp[1]=bp[1]; rp[2]=bp[2]; rp[3]=bp[3];
      sc[fi] = -1e30f;
    }
    __syncthreads();
  }
}

// 6. greedy NMS
__global__ void nms_kernel() {
  int b=blockIdx.x, t=threadIdx.x;
  __shared__ float x1s[30],y1s[30],x2s[30],y2s[30],ars[30];
  __shared__ int keep[30];
  if (t<30) {
    const float* rp=&g_rois[(b*KTOP+t)*4];
    x1s[t]=rp[0]; y1s[t]=rp[1]; x2s[t]=rp[2]; y2s[t]=rp[3];
    ars[t]=(rp[2]-rp[0])*(rp[3]-rp[1]); keep[t]=1;
  }
  __syncwarp();
  for (int i=0;i<KTOP;i++) {
    if (t<30 && t>i && keep[i]) {
      float iw=fmaxf(fminf(x2s[i],x2s[t])-fmaxf(x1s[i],x1s[t]),0.f);
      float ih=fmaxf(fminf(y2s[i],y2s[t])-fmaxf(y1s[i],y1s[t]),0.f);
      float inter=iw*ih;
      if (inter/(ars[i]+ars[t]-inter) > 0.85f) keep[t]=0;
    }
    __syncwarp();
  }
  if (t<30) g_valid[b*KTOP+t]=keep[t];
}

// 7. integral images
__global__ void integral_rows_kernel(const float* __restrict__ gt) {
  int b=blockIdx.x, t=threadIdx.x;
  float* I = g_I + (size_t)b*66049;
  I[t]=0.f; if (t==0) I[256]=0.f;
  const float* g = gt + (size_t)b*65536 + (size_t)t*256;
  float* row = I + (size_t)(t+1)*257;
  row[0]=0.f; float run=0.f;
  for (int x=0;x<256;x++){ run+=g[x]; row[x+1]=run; }
}
__global__ void integral_cols_kernel() {
  int b=blockIdx.x, x=threadIdx.x+1;
  float* I = g_I + (size_t)b*66049;
  float run=0.f;
  for (int y=1;y<=256;y++){ run += I[(size_t)y*257+x]; I[(size_t)y*257+x]=run; }
}

// 8. ROI labels
__global__ void labels_kernel() {
  int r = blockIdx.x*blockDim.x + threadIdx.x;
  if (r>=NROI) return;
  int b = r/KTOP;
  const float* roi=&g_rois[r*4];
  int x1=min(max((int)roi[0],0),256), y1=min(max((int)roi[1],0),256);
  int x2=min(max((int)roi[2],0),256), y2=min(max((int)roi[3],0),256);
  const float* I = g_I + (size_t)b*66049;
  float s = I[(size_t)y2*257+x2]-I[(size_t)y1*257+x2]-I[(size_t)y2*257+x1]+I[(size_t)y1*257+x1];
  int cnt=(y2-y1)*(x2-x1);
  g_labels[r] = (cnt>0) ? ((s/(float)max(cnt,1))>0.5f ? 1 : 0) : 0;
}

// 9. ROI align
__global__ void roi_align_kernel() {
  int r=blockIdx.x, t=threadIdx.x, b=r/KTOP;
  __shared__ float w00[49],w01[49],w10[49],w11[49];
  __shared__ int o00[49],o01[49],o10[49],o11[49],pok[49];
  if (t<49) {
    const float* roi=&g_rois[r*4];
    const float sc=1.f/16.f;
    float x1=roi[0]*sc, y1=roi[1]*sc;
    float rw=fmaxf(roi[2]*sc-x1,1.f), rh=fmaxf(roi[3]*sc-y1,1.f);
    int p=t/7, q=t-p*7;
    float X=x1+(q+0.5f)*(rw/7.f), Y=y1+(p+0.5f)*(rh/7.f);
    int ok = (Y>-1.f)&&(Y<16.f)&&(X>-1.f)&&(X<16.f);
    float Xc=fminf(fmaxf(X,0.f),15.f), Yc=fminf(fmaxf(Y,0.f),15.f);
    int x0=(int)floorf(Xc), y0=(int)floorf(Yc);
    int x1i=min(x0+1,15), y1i=min(y0+1,15);
    float lx=Xc-(float)x0, ly=Yc-(float)y0, hx=1.f-lx, hy=1.f-ly;
    w00[t]=hy*hx; w01[t]=hy*lx; w10[t]=ly*hx; w11[t]=ly*lx;
    o00[t]=(y0*16+x0)*CDIM; o01[t]=(y0*16+x1i)*CDIM;
    o10[t]=(y1i*16+x0)*CDIM; o11[t]=(y1i*16+x1i)*CDIM;
    pok[t]=ok;
  }
  __syncthreads();
  const float* Sb = g_S + (size_t)b*NPOS*CDIM;
  float a0=0,a1=0,a2=0,a3=0;
  for (int pt=0;pt<49;pt++) {
    if (!pok[pt]) continue;
    const float *p00=Sb+o00[pt],*p01=Sb+o01[pt],*p10=Sb+o10[pt],*p11=Sb+o11[pt];
    float W00=w00[pt],W01=w01[pt],W10=w10[pt],W11=w11[pt];
    a0 += W00*p00[t]     + W01*p01[t]     + W10*p10[t]     + W11*p11[t];
    a1 += W00*p00[t+256] + W01*p01[t+256] + W10*p10[t+256] + W11*p11[t+256];
    a2 += W00*p00[t+512] + W01*p01[t+512] + W10*p10[t+512] + W11*p11[t+512];
    a3 += W00*p00[t+768] + W01*p01[t+768] + W10*p10[t+768] + W11*p11[t+768];
  }
  float* out = g_pooled + (size_t)r*CDIM;
  out[t]=a0/49.f; out[t+256]=a1/49.f; out[t+512]=a2/49.f; out[t+768]=a3/49.f;
}

// 10. generic tiled C = A*B^T (+bias, relu). 64x64 tiles.
__global__ __launch_bounds__(256) void gemm_abt_kernel(const float* __restrict__ A,
                                                       const float* __restrict__ Bm,
                                                       float* __restrict__ C,
                                                       int K, int N,
                                                       const float* __restrict__ bias,
                                                       int relu) {
  const int bm = blockIdx.y*64, bn = blockIdx.x*64, tid = threadIdx.x;
  __shared__ float As[16][68];
  __shared__ float Bs[16][68];
  const int lr = tid>>2, lk = (tid&3)<<2;
  const int tm = (tid>>4)<<2, tn = (tid&15)<<2;
  float acc[4][4];
#pragma unroll
  for (int r=0;r<4;r++)
#pragma unroll
    for (int c=0;c<4;c++) acc[r][c]=0.f;
  for (int k0=0;k0<K;k0+=16) {
    float4 a4 = *(const float4*)&A[(size_t)(bm+lr)*K + k0+lk];
    float4 b4 = *(const float4*)&Bm[(size_t)(bn+lr)*K + k0+lk];
    __syncthreads();
    As[lk+0][lr]=a4.x; As[lk+1][lr]=a4.y; As[lk+2][lr]=a4.z; As[lk+3][lr]=a4.w;
    Bs[lk+0][lr]=b4.x; Bs[lk+1][lr]=b4.y; Bs[lk+2][lr]=b4.z; Bs[lk+3][lr]=b4.w;
    __syncthreads();
#pragma unroll
    for (int kk=0;kk<16;kk++) {
      float4 av=*(const float4*)&As[kk][tm];
      float4 bv=*(const float4*)&Bs[kk][tn];
      float aa[4]={av.x,av.y,av.z,av.w}, bb[4]={bv.x,bv.y,bv.z,bv.w};
#pragma unroll
      for (int r=0;r<4;r++)
#pragma unroll
        for (int c=0;c<4;c++) acc[r][c]+=aa[r]*bb[c];
    }
  }
#pragma unroll
  for (int r=0;r<4;r++) {
    size_t off=(size_t)(bm+tm+r)*N + bn+tn;
#pragma unroll
    for (int c=0;c<4;c++) {
      float v=acc[r][c] + (bias ? bias[bn+tn+c] : 0.f);
      if (relu) v=fmaxf(v,0.f);
      C[off+c]=v;
    }
  }
}

// 11. row L2 normalize
__global__ void normalize_kernel() {
  int i=blockIdx.x, t=threadIdx.x;
  float v = g_proj[(size_t)i*PROJD+t];
  __shared__ float red[256];
  red[t]=v*v; __syncthreads();
  for (int off=128;off>0;off>>=1){ if (t<off) red[t]+=red[t+off]; __syncthreads(); }
  float nrm = fmaxf(sqrtf(red[0]), 1e-12f);
  g_nf[(size_t)i*PROJD+t] = v/nrm;
}

// 12. SupCon per-row from precomputed sim
__global__ void supcon_kernel() {
  int i=blockIdx.x, t=threadIdx.x;
  __shared__ float rp[256], ra[256]; __shared__ int rc[256];
  int li=g_labels[i], vi=g_valid[i];
  const float* simr = g_sim + (size_t)i*NROI;
  float psum=0.f, asum=0.f; int pcnt=0;
  for (int j=t;j<NROI;j+=256) {
    float es = expf(simr[j]*(1.f/0.07f));
    int vj=g_valid[j];
    int nd = (j!=i), vv = vi && vj;
    int isp = (g_labels[j]==li) && nd && vv;
    int ism = nd && vv;
    if (isp) { psum+=es; pcnt++; }
    if (ism) asum+=es;
  }
  rp[t]=psum; ra[t]=asum; rc[t]=pcnt; __syncthreads();
  for (int off=128;off>0;off>>=1) {
    if (t<off){ rp[t]+=rp[t+off]; ra[t]+=ra[t+off]; rc[t]+=rc[t+off]; }
    __syncthreads();
  }
  if (t==0) {
    float ratio = rp[0]/(ra[0]+1e-12f);
    float l = -logf(ratio+1e-12f);
    int active = vi && (rc[0]>0);
    g_rowl[i] = active ? l : 0.f;
    g_rowact[i] = active;
  }
}

// 13. finalize
__global__ void finalize_kernel(float* out) {
  int t=threadIdx.x;
  __shared__ float rl[256]; __shared__ int rc[256];
  float s=0.f; int c=0;
  for (int i=t;i<NROI;i+=256){ s+=g_rowl[i]; c+=g_rowact[i]; }
  rl[t]=s; rc[t]=c; __syncthreads();
  for (int off=128;off>0;off>>=1){ if (t<off){ rl[t]+=rl[t+off]; rc[t]+=rc[t+off]; } __syncthreads(); }
  if (t==0) out[0] = (rc[0]>0) ? rl[0]/(float)max(rc[0],1) : 0.f;
}

extern "C" void kernel_launch(void* const* d_in, const int* in_sizes, int n_in,
                              void* d_out, int out_size) {
  const float* clip   = (const float*)d_in[0];
  const float* gt     = (const float*)d_in[1];
  const float* conv_w = (const float*)d_in[2];
  const float* conv_b = (const float*)d_in[3];
  const float* cls_w  = (const float*)d_in[4];
  const float* cls_b  = (const float*)d_in[5];
  const float* reg_w  = (const float*)d_in[6];
  const float* reg_b  = (const float*)d_in[7];
  const float* pw1    = (const float*)d_in[8];
  const float* pb1    = (const float*)d_in[9];
  const float* pw2    = (const float*)d_in[10];
  const float* pb2    = (const float*)d_in[11];

  cudaFuncSetAttribute(conv_mma_kernel, cudaFuncAttributeMaxDynamicSharedMemorySize, CONV_SMEM);

  float* g_pooled_p; cudaGetSymbolAddress((void**)&g_pooled_p, g_pooled);
  float* g_h_p;      cudaGetSymbolAddress((void**)&g_h_p, g_h);
  float* g_proj_p;   cudaGetSymbolAddress((void**)&g_proj_p, g_proj);
  float* g_nf_p;     cudaGetSymbolAddress((void**)&g_nf_p, g_nf);
  float* g_sim_p;    cudaGetSymbolAddress((void**)&g_sim_p, g_sim);

  build_split_spatial<<<MROWS, 256>>>(clip);
  split_w_kernel<<<(OC*CDIM)/256, 256>>>(conv_w);
  conv_mma_kernel<<<dim3(4,64), 256, CONV_SMEM>>>(conv_b);
  heads_kernel<<<MROWS/4, 256>>>(cls_w, cls_b, reg_w, reg_b);
  topk_kernel<<<NB, 256>>>();
  nms_kernel<<<NB, 32>>>();
  integral_rows_kernel<<<NB, 256>>>(gt);
  integral_cols_kernel<<<NB, 256>>>();
  labels_kernel<<<(NROI+255)/256, 256>>>();
  roi_align_kernel<<<NROI, 256>>>();
  gemm_abt_kernel<<<dim3(4,15), 256>>>(g_pooled_p, pw1, g_h_p, CDIM, PROJD, pb1, 1);
  gemm_abt_kernel<<<dim3(4,15), 256>>>(g_h_p, pw2, g_proj_p, PROJD, PROJD, pb2, 0);
  normalize_kernel<<<NROI, 256>>>();
  gemm_abt_kernel<<<dim3(15,15), 256>>>(g_nf_p, g_nf_p, g_sim_p, PROJD, NROI, (const float*)nullptr, 0);
  supcon_kernel<<<NROI, 256>>>();
  finalize_kernel<<<1, 256>>>((float*)d_out);
}

// round 17
// speedup vs baseline: 3.0949x; 1.1105x over previous
#include <cuda_runtime.h>
#include <cuda_fp16.h>
#include <math.h>
#include <stdint.h>

#define NB 32
#define CDIM 1024
#define FE 16
#define NANC 9
#define KTOP 30
#define NROI (NB*KTOP)
#define PROJD 256
#define OC 512
#define NPOS (FE*FE)
#define MROWS (NB*NPOS)

__device__ float g_S[MROWS*CDIM];
__device__ float g_X[MROWS*OC];
__device__ float g_Xp[4][MROWS*OC];
__device__ float g_hw[48*OC];
__device__ float g_hb[48];
__device__ float g_hd[MROWS*48];
__device__ float g_scores[NB*NPOS*NANC];
__device__ float g_boxes[NB*NPOS*NANC*4];
__device__ float g_rois[NROI*4];
__device__ int   g_valid[NROI];
__device__ float g_I[NB*257*257];
__device__ float g_pooled[NROI*CDIM];
__device__ float g_h[NROI*PROJD];
__device__ float g_proj[NROI*PROJD];
__device__ float g_nf[NROI*PROJD];
__device__ float g_sim[NROI*NROI];
__device__ int   g_labels[NROI];
__device__ float g_rowl[NROI];
__device__ int   g_rowact[NROI];

// fp16 2-way splits (residual pre-scaled by 2048)
__device__ __align__(16) __half gA0[MROWS*CDIM];
__device__ __align__(16) __half gA1[MROWS*CDIM];
__device__ __align__(16) __half gB0[9*OC*CDIM];
__device__ __align__(16) __half gB1[9*OC*CDIM];

__device__ __forceinline__ uint32_t smem_u32(const void* p) {
  uint32_t a;
  asm("{ .reg .u64 t; cvta.to.shared.u64 t, %1; cvt.u32.u64 %0, t; }" : "=r"(a) : "l"(p));
  return a;
}

// 1. spatial: clip[1+p][b][c] -> g_S (fp32) + fp16 split
__global__ void build_split_spatial(const float* __restrict__ clip) {
  int bx = blockIdx.x; int b = bx >> 8, p = bx & 255;
  const float* src = clip + (size_t)(1+p)*NB*CDIM + (size_t)b*CDIM;
#pragma unroll
  for (int q = 0; q < 4; q++) {
    int c = threadIdx.x + q*256;
    float v = src[c];
    size_t di = (size_t)bx*CDIM + c;
    g_S[di] = v;
    __half h = __float2half(v);
    float r1 = (v - __half2float(h)) * 2048.f;
    gA0[di] = h; gA1[di] = __float2half(r1);
  }
}

// 2. weights conv_w[o][c][t] -> gB{0,1}[t][o][c]
__global__ void split_w_kernel(const float* __restrict__ conv_w) {
  int e = blockIdx.x*256 + threadIdx.x; // o*1024+c
  int o = e >> 10, c = e & 1023;
  const float* src = conv_w + (size_t)e*9;
#pragma unroll
  for (int t = 0; t < 9; t++) {
    float v = src[t];
    __half h = __float2half(v);
    float r1 = (v - __half2float(h)) * 2048.f;
    size_t di = ((size_t)t*OC + o)*CDIM + c;
    gB0[di] = h; gB1[di] = __float2half(r1);
  }
}

// 2b. pad head weights into [48][512] (+bias[48])
__global__ void pad_head_w(const float* __restrict__ cls_w, const float* __restrict__ cls_b,
                           const float* __restrict__ reg_w, const float* __restrict__ reg_b) {
  int e = blockIdx.x*256 + threadIdx.x; // < 48*512
  int row = e >> 9, c = e & 511;
  float v = 0.f;
  if (row < 9) v = cls_w[row*OC + c];
  else if (row < 45) v = reg_w[(row-9)*OC + c];
  g_hw[e] = v;
  if (c == 0) {
    float bv = 0.f;
    if (row < 9) bv = cls_b[row];
    else if (row < 45) bv = reg_b[row-9];
    g_hb[row] = bv;
  }
}

// 3. conv 3x3 via mma.sync fp16, 2-way split, 3 chains, fp32 acc, split-K x4.
#define ASTRIDE 48
#define SPL_SZ (128*ASTRIDE)
#define STAGE_SZ (4*SPL_SZ)
#define CONV_SMEM (4*STAGE_SZ)

#define CPA16(dst, src, sz) \
  asm volatile("cp.async.cg.shared.global [%0], [%1], 16, %2;" :: "r"(dst), "l"(src), "r"(sz))
#define LDSM4(r0,r1,r2,r3,addr) \
  asm volatile("ldmatrix.sync.aligned.m8n8.x4.shared.b16 {%0,%1,%2,%3}, [%4];" \
    : "=r"(r0),"=r"(r1),"=r"(r2),"=r"(r3) : "r"(addr))
#define MMA16816(d0,d1,d2,d3,a0,a1,a2,a3,b0,b1) \
  asm volatile("mma.sync.aligned.m16n8k16.row.col.f32.f16.f16.f32 " \
    "{%0,%1,%2,%3}, {%4,%5,%6,%7}, {%8,%9}, {%0,%1,%2,%3};" \
    : "+f"(d0),"+f"(d1),"+f"(d2),"+f"(d3) \
    : "r"(a0),"r"(a1),"r"(a2),"r"(a3),"r"(b0),"r"(b1))

__global__ void __launch_bounds__(256, 1) conv_mma_kernel() {
  extern __shared__ __align__(128) char smem[];
  uint32_t sb = smem_u32(smem);
  const int tid = threadIdx.x, wid = tid >> 5, lane = tid & 31;
  const int bn = blockIdx.x*128, bm = blockIdx.y*128, kz = blockIdx.z;
  const int wm = (wid >> 2)*64, wn = (wid & 3)*32;
  const int s0 = kz*144, s1 = s0 + 144;

  const int lrow = tid >> 1, lchunk = tid & 1;
  const int am = bm + lrow;
  const int ab = am >> 8, apos = am & 255, api = apos >> 4, apj = apos & 15;

  float accP[4][4][4], accQ[4][4][4];
#pragma unroll
  for (int i = 0; i < 4; i++)
#pragma unroll
    for (int j = 0; j < 4; j++)
#pragma unroll
      for (int k = 0; k < 4; k++) { accP[i][j][k] = 0.f; accQ[i][j][k] = 0.f; }

  const __half* gAp[2] = {gA0, gA1};
  const __half* gBp[2] = {gB0, gB1};

  auto issue = [&](int s) {
    uint32_t dst = sb + (uint32_t)(s & 3)*STAGE_SZ;
    int tap = s >> 6, kc = s & 63;
    int di = tap/3 - 1, dj = tap - (tap/3)*3 - 1;
    int ii = api + di, jj = apj + dj;
    bool ok = ((unsigned)ii < 16u) && ((unsigned)jj < 16u);
    size_t asrc = ok ? ((size_t)((ab<<8)+(ii<<4)+jj))*CDIM + kc*16 + lchunk*8 : 0;
    int asz = ok ? 16 : 0;
    uint32_t adst = dst + lrow*ASTRIDE + lchunk*16;
    CPA16(adst + 0*SPL_SZ, gAp[0] + asrc, asz);
    CPA16(adst + 1*SPL_SZ, gAp[1] + asrc, asz);
    size_t bsrc = ((size_t)tap*OC + bn + lrow)*CDIM + kc*16 + lchunk*8;
    uint32_t bdst = dst + 2*SPL_SZ + lrow*ASTRIDE + lchunk*16;
    CPA16(bdst + 0*SPL_SZ, gBp[0] + bsrc, 16);
    CPA16(bdst + 1*SPL_SZ, gBp[1] + bsrc, 16);
    asm volatile("cp.async.commit_group;" ::: "memory");
  };

  issue(s0); issue(s0+1); issue(s0+2);

  const uint32_t a_off = (uint32_t)(wm + (lane & 15))*ASTRIDE + (uint32_t)(lane >> 4)*16;
  const uint32_t b_off = (uint32_t)(wn + (lane & 7) + ((lane >> 4) << 3))*ASTRIDE
                       + (uint32_t)((lane >> 3) & 1)*16;

  for (int s = s0; s < s1; s++) {
    asm volatile("cp.async.wait_group 2;" ::: "memory");
    __syncthreads();
    uint32_t base = sb + (uint32_t)(s & 3)*STAGE_SZ;

    uint32_t Ar[2][4][4];
    uint32_t Br[2][4][2];
#pragma unroll
    for (int p = 0; p < 2; p++) {
#pragma unroll
      for (int i = 0; i < 4; i++) {
        uint32_t ad = base + p*SPL_SZ + a_off + (uint32_t)(i*16)*ASTRIDE;
        LDSM4(Ar[p][i][0], Ar[p][i][1], Ar[p][i][2], Ar[p][i][3], ad);
      }
#pragma unroll
      for (int j = 0; j < 2; j++) {
        uint32_t bd = base + (2+p)*SPL_SZ + b_off + (uint32_t)(j*16)*ASTRIDE;
        LDSM4(Br[p][2*j][0], Br[p][2*j][1], Br[p][2*j+1][0], Br[p][2*j+1][1], bd);
      }
    }
    if (s + 3 < s1) issue(s + 3);
    else asm volatile("cp.async.commit_group;" ::: "memory");

#pragma unroll
    for (int i = 0; i < 4; i++)
#pragma unroll
      for (int jn = 0; jn < 4; jn++) {
        MMA16816(accP[i][jn][0], accP[i][jn][1], accP[i][jn][2], accP[i][jn][3],
                 Ar[0][i][0], Ar[0][i][1], Ar[0][i][2], Ar[0][i][3],
                 Br[0][jn][0], Br[0][jn][1]);
        MMA16816(accQ[i][jn][0], accQ[i][jn][1], accQ[i][jn][2], accQ[i][jn][3],
                 Ar[0][i][0], Ar[0][i][1], Ar[0][i][2], Ar[0][i][3],
                 Br[1][jn][0], Br[1][jn][1]);
        MMA16816(accQ[i][jn][0], accQ[i][jn][1], accQ[i][jn][2], accQ[i][jn][3],
                 Ar[1][i][0], Ar[1][i][1], Ar[1][i][2], Ar[1][i][3],
                 Br[0][jn][0], Br[0][jn][1]);
      }
  }

  float* Xp = g_Xp[kz];
  const int gi = lane >> 2, t4 = lane & 3;
  const float RS = 1.f/2048.f;
#pragma unroll
  for (int i = 0; i < 4; i++) {
#pragma unroll
    for (int jn = 0; jn < 4; jn++) {
      int r0 = bm + wm + i*16 + gi;
      int c0 = bn + wn + jn*8 + t4*2;
      Xp[(size_t)r0*OC + c0]         = accP[i][jn][0] + accQ[i][jn][0]*RS;
      Xp[(size_t)r0*OC + c0 + 1]     = accP[i][jn][1] + accQ[i][jn][1]*RS;
      Xp[(size_t)(r0+8)*OC + c0]     = accP[i][jn][2] + accQ[i][jn][2]*RS;
      Xp[(size_t)(r0+8)*OC + c0 + 1] = accP[i][jn][3] + accQ[i][jn][3]*RS;
    }
  }
}

// 3b. combine split-K partials + bias + relu
__global__ void conv_combine(const float* __restrict__ convb) {
  int idx = blockIdx.x*256 + threadIdx.x;  // < MROWS*OC
  float v = ((g_Xp[0][idx] + g_Xp[1][idx]) + g_Xp[2][idx]) + g_Xp[3][idx];
  g_X[idx] = fmaxf(v + convb[idx & 511], 0.f);
}

// 4a. heads GEMM: g_hd[8192,48] = g_X[8192,512] @ g_hw^T + g_hb
__global__ __launch_bounds__(256) void heads_gemm_kernel() {
  const int bm = blockIdx.x*64, tid = threadIdx.x;
  __shared__ float As[16][68];
  __shared__ float Bs[16][52];
  const int lr = tid>>2, lk = (tid&3)<<2;
  const int tm = (tid>>4)<<2, tn = (tid&15)*3;
  float acc[4][3];
#pragma unroll
  for (int r=0;r<4;r++)
#pragma unroll
    for (int c=0;c<3;c++) acc[r][c]=0.f;
  for (int k0=0;k0<OC;k0+=16) {
    float4 a4 = *(const float4*)&g_X[(size_t)(bm+lr)*OC + k0+lk];
    float4 b4 = make_float4(0,0,0,0);
    if (tid < 192) b4 = *(const float4*)&g_hw[(size_t)lr*OC + k0+lk];
    __syncthreads();
    As[lk+0][lr]=a4.x; As[lk+1][lr]=a4.y; As[lk+2][lr]=a4.z; As[lk+3][lr]=a4.w;
    if (tid < 192) {
      Bs[lk+0][lr]=b4.x; Bs[lk+1][lr]=b4.y; Bs[lk+2][lr]=b4.z; Bs[lk+3][lr]=b4.w;
    }
    __syncthreads();
#pragma unroll
    for (int kk=0;kk<16;kk++) {
      float a0=As[kk][tm], a1=As[kk][tm+1], a2=As[kk][tm+2], a3=As[kk][tm+3];
      float b0=Bs[kk][tn], b1=Bs[kk][tn+1], b2=Bs[kk][tn+2];
      acc[0][0]+=a0*b0; acc[0][1]+=a0*b1; acc[0][2]+=a0*b2;
      acc[1][0]+=a1*b0; acc[1][1]+=a1*b1; acc[1][2]+=a1*b2;
      acc[2][0]+=a2*b0; acc[2][1]+=a2*b1; acc[2][2]+=a2*b2;
      acc[3][0]+=a3*b0; acc[3][1]+=a3*b1; acc[3][2]+=a3*b2;
    }
  }
#pragma unroll
  for (int r=0;r<4;r++)
#pragma unroll
    for (int c=0;c<3;c++)
      g_hd[(size_t)(bm+tm+r)*48 + tn+c] = acc[r][c] + g_hb[tn+c];
}

// 4b. decode: one thread per (position, anchor)
__global__ void decode_kernel() {
  int g = blockIdx.x*256 + threadIdx.x;  // < 8192*9
  if (g >= MROWS*NANC) return;
  int m = g / 9, a = g - m*9;
  int b = m>>8, pos = m&255, i = pos>>4, j = pos&15;
  const float* hd = g_hd + (size_t)m*48;
  float cls = hd[a];
  float r0 = hd[9+a*4+0], r1 = hd[9+a*4+1], r2 = hd[9+a*4+2], r3 = hd[9+a*4+3];
  const double scl[3]={8.0,16.0,32.0}, rat[3]={0.5,1.0,2.0};
  double s=scl[a/3], rr=rat[a-(a/3)*3];
  double wD=s*sqrt(rr), hD=s/sqrt(rr);
  double xcD=(j+0.5)*16.0, ycD=(i+0.5)*16.0;
  float ax1=(float)(xcD-wD*0.5), ay1=(float)(ycD-hD*0.5);
  float ax2=(float)(xcD+wD*0.5), ay2=(float)(ycD+hD*0.5);
  float aw=ax2-ax1, ah=ay2-ay1, ctx=ax1+0.5f*aw, cty=ay1+0.5f*ah;
  float cx=r0*aw+ctx, cy=r1*ah+cty;
  float pw=expf(r2)*aw, ph=expf(r3)*ah;
  float x1=fminf(fmaxf(cx-0.5f*pw,0.f),256.f), y1=fminf(fmaxf(cy-0.5f*ph,0.f),256.f);
  float x2=fminf(fmaxf(cx+0.5f*pw,0.f),256.f), y2=fminf(fmaxf(cy+0.5f*ph,0.f),256.f);
  if (x2-x1<1.f) x2=x1+1.f;
  if (y2-y1<1.f) y2=y1+1.f;
  int aidx = pos*9+a;
  g_scores[b*2304+aidx] = 1.f/(1.f+expf(-cls));
  float* bp = &g_boxes[((size_t)b*2304+aidx)*4];
  bp[0]=x1; bp[1]=y1; bp[2]=x2; bp[3]=y2;
}

// 5. stable top-30: smem scores, selected -> -inf, warp-shuffle argmax
__global__ void topk_kernel() {
  int b = blockIdx.x, tid = threadIdx.x, w = tid>>5, lane = tid&31;
  __shared__ float sc[2304];
  __shared__ float wv[8]; __shared__ int wi[8];
  const float* gs = g_scores + (size_t)b*2304;
  for (int e = tid; e < 2304; e += 256) sc[e] = gs[e];
  __syncthreads();
  for (int k=0;k<KTOP;k++) {
    float bv=-1e30f; int bi=1<<30;
    for (int e=tid;e<2304;e+=256) {
      float v=sc[e];
      if (v>bv || (v==bv && e<bi)) { bv=v; bi=e; }
    }
#pragma unroll
    for (int o=16;o>0;o>>=1) {
      float ov=__shfl_down_sync(0xffffffffu,bv,o);
      int   oi=__shfl_down_sync(0xffffffffu,bi,o);
      if (ov>bv || (ov==bv && oi<bi)) { bv=ov; bi=oi; }
    }
    if (lane==0) { wv[w]=bv; wi[w]=bi; }
    __syncthreads();
    if (tid==0) {
      float fv=wv[0]; int fi=wi[0];
#pragma unroll
      for (int q=1;q<8;q++) {
        if (wv[q]>fv || (wv[q]==fv && wi[q]<fi)) { fv=wv[q]; fi=wi[q]; }
      }
      const float* bp=&g_boxes[((size_t)b*2304+fi)*4];
      float* rp=&g_rois[(b*KTOP+k)*4];
      rp[0]=bp[0]; rp[1]=bp[1]; rp[2]=bp[2]; rp[3]=bp[3];
      sc[fi] = -1e30f;
    }
    __syncthreads();
  }
}

// 6. greedy NMS
__global__ void nms_kernel() {
  int b=blockIdx.x, t=threadIdx.x;
  __shared__ float x1s[30],y1s[30],x2s[30],y2s[30],ars[30];
  __shared__ int keep[30];
  if (t<30) {
    const float* rp=&g_rois[(b*KTOP+t)*4];
    x1s[t]=rp[0]; y1s[t]=rp[1]; x2s[t]=rp[2]; y2s[t]=rp[3];
    ars[t]=(rp[2]-rp[0])*(rp[3]-rp[1]); keep[t]=1;
  }
  __syncwarp();
  for (int i=0;i<KTOP;i++) {
    if (t<30 && t>i && keep[i]) {
      float iw=fmaxf(fminf(x2s[i],x2s[t])-fmaxf(x1s[i],x1s[t]),0.f);
      float ih=fmaxf(fminf(y2s[i],y2s[t])-fmaxf(y1s[i],y1s[t]),0.f);
      float inter=iw*ih;
      if (inter/(ars[i]+ars[t]-inter) > 0.85f) keep[t]=0;
    }
    __syncwarp();
  }
  if (t<30) g_valid[b*KTOP+t]=keep[t];
}

// 7. integral images
__global__ void integral_rows_kernel(const float* __restrict__ gt) {
  int b=blockIdx.x, t=threadIdx.x;
  float* I = g_I + (size_t)b*66049;
  I[t]=0.f; if (t==0) I[256]=0.f;
  const float* g = gt + (size_t)b*65536 + (size_t)t*256;
  float* row = I + (size_t)(t+1)*257;
  row[0]=0.f; float run=0.f;
  for (int x=0;x<256;x++){ run+=g[x]; row[x+1]=run; }
}
__global__ void integral_cols_kernel() {
  int b=blockIdx.x, x=threadIdx.x+1;
  float* I = g_I + (size_t)b*66049;
  float run=0.f;
  for (int y=1;y<=256;y++){ run += I[(size_t)y*257+x]; I[(size_t)y*257+x]=run; }
}

// 8. ROI labels
__global__ void labels_kernel() {
  int r = blockIdx.x*blockDim.x + threadIdx.x;
  if (r>=NROI) return;
  int b = r/KTOP;
  const float* roi=&g_rois[r*4];
  int x1=min(max((int)roi[0],0),256), y1=min(max((int)roi[1],0),256);
  int x2=min(max((int)roi[2],0),256), y2=min(max((int)roi[3],0),256);
  const float* I = g_I + (size_t)b*66049;
  float s = I[(size_t)y2*257+x2]-I[(size_t)y1*257+x2]-I[(size_t)y2*257+x1]+I[(size_t)y1*257+x1];
  int cnt=(y2-y1)*(x2-x1);
  g_labels[r] = (cnt>0) ? ((s/(float)max(cnt,1))>0.5f ? 1 : 0) : 0;
}

// 9. ROI align
__global__ void roi_align_kernel() {
  int r=blockIdx.x, t=threadIdx.x, b=r/KTOP;
  __shared__ float w00[49],w01[49],w10[49],w11[49];
  __shared__ int o00[49],o01[49],o10[49],o11[49],pok[49];
  if (t<49) {
    const float* roi=&g_rois[r*4];
    const float sc=1.f/16.f;
    float x1=roi[0]*sc, y1=roi[1]*sc;
    float rw=fmaxf(roi[2]*sc-x1,1.f), rh=fmaxf(roi[3]*sc-y1,1.f);
    int p=t/7, q=t-p*7;
    float X=x1+(q+0.5f)*(rw/7.f), Y=y1+(p+0.5f)*(rh/7.f);
    int ok = (Y>-1.f)&&(Y<16.f)&&(X>-1.f)&&(X<16.f);
    float Xc=fminf(fmaxf(X,0.f),15.f), Yc=fminf(fmaxf(Y,0.f),15.f);
    int x0=(int)floorf(Xc), y0=(int)floorf(Yc);
    int x1i=min(x0+1,15), y1i=min(y0+1,15);
    float lx=Xc-(float)x0, ly=Yc-(float)y0, hx=1.f-lx, hy=1.f-ly;
    w00[t]=hy*hx; w01[t]=hy*lx; w10[t]=ly*hx; w11[t]=ly*lx;
    o00[t]=(y0*16+x0)*CDIM; o01[t]=(y0*16+x1i)*CDIM;
    o10[t]=(y1i*16+x0)*CDIM; o11[t]=(y1i*16+x1i)*CDIM;
    pok[t]=ok;
  }
  __syncthreads();
  const float* Sb = g_S + (size_t)b*NPOS*CDIM;
  float a0=0,a1=0,a2=0,a3=0;
  for (int pt=0;pt<49;pt++) {
    if (!pok[pt]) continue;
    const float *p00=Sb+o00[pt],*p01=Sb+o01[pt],*p10=Sb+o10[pt],*p11=Sb+o11[pt];
    float W00=w00[pt],W01=w01[pt],W10=w10[pt],W11=w11[pt];
    a0 += W00*p00[t]     + W01*p01[t]     + W10*p10[t]     + W11*p11[t];
    a1 += W00*p00[t+256] + W01*p01[t+256] + W10*p10[t+256] + W11*p11[t+256];
    a2 += W00*p00[t+512] + W01*p01[t+512] + W10*p10[t+512] + W11*p11[t+512];
    a3 += W00*p00[t+768] + W01*p01[t+768] + W10*p10[t+768] + W11*p11[t+768];
  }
  float* out = g_pooled + (size_t)r*CDIM;
  out[t]=a0/49.f; out[t+256]=a1/49.f; out[t+512]=a2/49.f; out[t+768]=a3/49.f;
}

// 10. generic tiled C = A*B^T (+bias, relu). 64x64 tiles.
__global__ __launch_bounds__(256) void gemm_abt_kernel(const float* __restrict__ A,
                                                       const float* __restrict__ Bm,
                                                       float* __restrict__ C,
                                                       int K, int N,
                                                       const float* __restrict__ bias,
                                                       int relu) {
  const int bm = blockIdx.y*64, bn = blockIdx.x*64, tid = threadIdx.x;
  __shared__ float As[16][68];
  __shared__ float Bs[16][68];
  const int lr = tid>>2, lk = (tid&3)<<2;
  const int tm = (tid>>4)<<2, tn = (tid&15)<<2;
  float acc[4][4];
#pragma unroll
  for (int r=0;r<4;r++)
#pragma unroll
    for (int c=0;c<4;c++) acc[r][c]=0.f;
  for (int k0=0;k0<K;k0+=16) {
    float4 a4 = *(const float4*)&A[(size_t)(bm+lr)*K + k0+lk];
    float4 b4 = *(const float4*)&Bm[(size_t)(bn+lr)*K + k0+lk];
    __syncthreads();
    As[lk+0][lr]=a4.x; As[lk+1][lr]=a4.y; As[lk+2][lr]=a4.z; As[lk+3][lr]=a4.w;
    Bs[lk+0][lr]=b4.x; Bs[lk+1][lr]=b4.y; Bs[lk+2][lr]=b4.z; Bs[lk+3][lr]=b4.w;
    __syncthreads();
#pragma unroll
    for (int kk=0;kk<16;kk++) {
      float4 av=*(const float4*)&As[kk][tm];
      float4 bv=*(const float4*)&Bs[kk][tn];
      float aa[4]={av.x,av.y,av.z,av.w}, bb[4]={bv.x,bv.y,bv.z,bv.w};
#pragma unroll
      for (int r=0;r<4;r++)
#pragma unroll
        for (int c=0;c<4;c++) acc[r][c]+=aa[r]*bb[c];
    }
  }
#pragma unroll
  for (int r=0;r<4;r++) {
    size_t off=(size_t)(bm+tm+r)*N + bn+tn;
#pragma unroll
    for (int c=0;c<4;c++) {
      float v=acc[r][c] + (bias ? bias[bn+tn+c] : 0.f);
      if (relu) v=fmaxf(v,0.f);
      C[off+c]=v;
    }
  }
}

// 11. row L2 normalize
__global__ void normalize_kernel() {
  int i=blockIdx.x, t=threadIdx.x;
  float v = g_proj[(size_t)i*PROJD+t];
  __shared__ float red[256];
  red[t]=v*v; __syncthreads();
  for (int off=128;off>0;off>>=1){ if (t<off) red[t]+=red[t+off]; __syncthreads(); }
  float nrm = fmaxf(sqrtf(red[0]), 1e-12f);
  g_nf[(size_t)i*PROJD+t] = v/nrm;
}

// 12. SupCon per-row from precomputed sim
__global__ void supcon_kernel() {
  int i=blockIdx.x, t=threadIdx.x;
  __shared__ float rp[256], ra[256]; __shared__ int rc[256];
  int li=g_labels[i], vi=g_valid[i];
  const float* simr = g_sim + (size_t)i*NROI;
  float psum=0.f, asum=0.f; int pcnt=0;
  for (int j=t;j<NROI;j+=256) {
    float es = expf(simr[j]*(1.f/0.07f));
    int vj=g_valid[j];
    int nd = (j!=i), vv = vi && vj;
    int isp = (g_labels[j]==li) && nd && vv;
    int ism = nd && vv;
    if (isp) { psum+=es; pcnt++; }
    if (ism) asum+=es;
  }
  rp[t]=psum; ra[t]=asum; rc[t]=pcnt; __syncthreads();
  for (int off=128;off>0;off>>=1) {
    if (t<off){ rp[t]+=rp[t+off]; ra[t]+=ra[t+off]; rc[t]+=rc[t+off]; }
    __syncthreads();
  }
  if (t==0) {
    float ratio = rp[0]/(ra[0]+1e-12f);
    float l = -logf(ratio+1e-12f);
    int active = vi && (rc[0]>0);
    g_rowl[i] = active ? l : 0.f;
    g_rowact[i] = active;
  }
}

// 13. finalize
__global__ void finalize_kernel(float* out) {
  int t=threadIdx.x;
  __shared__ float rl[256]; __shared__ int rc[256];
  float s=0.f; int c=0;
  for (int i=t;i<NROI;i+=256){ s+=g_rowl[i]; c+=g_rowact[i]; }
  rl[t]=s; rc[t]=c; __syncthreads();
  for (int off=128;off>0;off>>=1){ if (t<off){ rl[t]+=rl[t+off]; rc[t]+=rc[t+off]; } __syncthreads(); }
  if (t==0) out[0] = (rc[0]>0) ? rl[0]/(float)max(rc[0],1) : 0.f;
}

extern "C" void kernel_launch(void* const* d_in, const int* in_sizes, int n_in,
                              void* d_out, int out_size) {
  const float* clip   = (const float*)d_in[0];
  const float* gt     = (const float*)d_in[1];
  const float* conv_w = (const float*)d_in[2];
  const float* conv_b = (const float*)d_in[3];
  const float* cls_w  = (const float*)d_in[4];
  const float* cls_b  = (const float*)d_in[5];
  const float* reg_w  = (const float*)d_in[6];
  const float* reg_b  = (const float*)d_in[7];
  const float* pw1    = (const float*)d_in[8];
  const float* pb1    = (const float*)d_in[9];
  const float* pw2    = (const float*)d_in[10];
  const float* pb2    = (const float*)d_in[11];

  cudaFuncSetAttribute(conv_mma_kernel, cudaFuncAttributeMaxDynamicSharedMemorySize, CONV_SMEM);

  float* g_pooled_p; cudaGetSymbolAddress((void**)&g_pooled_p, g_pooled);
  float* g_h_p;      cudaGetSymbolAddress((void**)&g_h_p, g_h);
  float* g_proj_p;   cudaGetSymbolAddress((void**)&g_proj_p, g_proj);
  float* g_nf_p;     cudaGetSymbolAddress((void**)&g_nf_p, g_nf);
  float* g_sim_p;    cudaGetSymbolAddress((void**)&g_sim_p, g_sim);

  build_split_spatial<<<MROWS, 256>>>(clip);
  split_w_kernel<<<(OC*CDIM)/256, 256>>>(conv_w);
  pad_head_w<<<(48*OC)/256, 256>>>(cls_w, cls_b, reg_w, reg_b);
  conv_mma_kernel<<<dim3(4,64,4), 256, CONV_SMEM>>>();
  conv_combine<<<(MROWS*OC)/256, 256>>>(conv_b);
  heads_gemm_kernel<<<MROWS/64, 256>>>();
  decode_kernel<<<(MROWS*NANC+255)/256, 256>>>();
  topk_kernel<<<NB, 256>>>();
  nms_kernel<<<NB, 32>>>();
  integral_rows_kernel<<<NB, 256>>>(gt);
  integral_cols_kernel<<<NB, 256>>>();
  labels_kernel<<<(NROI+255)/256, 256>>>();
  roi_align_kernel<<<NROI, 256>>>();
  gemm_abt_kernel<<<dim3(4,15), 256>>>(g_pooled_p, pw1, g_h_p, CDIM, PROJD, pb1, 1);
  gemm_abt_kernel<<<dim3(4,15), 256>>>(g_h_p, pw2, g_proj_p, PROJD, PROJD, pb2, 0);
  normalize_kernel<<<NROI, 256>>>();
  gemm_abt_kernel<<<dim3(15,15), 256>>>(g_nf_p, g_nf_p, g_sim_p, PROJD, NROI, (const float*)nullptr, 0);
  supcon_kernel<<<NROI, 256>>>();
  finalize_kernel<<<1, 256>>>((float*)d_out);
}